// round 8
// baseline (speedup 1.0000x reference)
#include <cuda_runtime.h>
#include <cuda_bf16.h>
#include <math.h>
#include <stdint.h>

// ---------------------------------------------------------------------------
#define NA   256
#define HID  128
#define ACT  5
#define NH   4
#define DD   144
#define EE   576
#define HDH  144
#define OBS_RX 4
#define OBS_RY 2
#define NB   148          // persistent grid, 1 CTA/SM
#define NTH  128          // 4 warps

// smem staging (bytes): bf16 rows padded to 144B (36 uints; (4g+tg)%32 distinct
// -> conflict-free fragment reads)
#define PITCHU 36                      // uints per row
#define OFF_AH 0
#define OFF_AL (128 * 144)             // 18432
#define OFF_BH (2 * 128 * 144)         // 36864
#define OFF_BL (2 * 128 * 144 + 32 * 144)
#define SMEM_DYN (2 * 128 * 144 + 2 * 32 * 144)   // 46080

// ---------------------------------------------------------------------------
__device__ __align__(16) float    g_C[NA * DD];
__device__ unsigned g_mask[NA * 8];
__device__ __align__(16) float    g_P[3][NA * EE];
__device__ __align__(16) float    g_Q[3][NA * EE];
__device__ __align__(16) float    g_S[NH * NA * NA];
__device__ __align__(16) float    g_G[NA * EE];
__device__ float    g_cnt[NA];
__device__ __align__(16) float    g_Wfin[EE * 6];
__device__ float    g_bfin[6];
__device__ unsigned          g_bar_count;
__device__ volatile unsigned g_bar_sense;

// ---------------------------------------------------------------------------
__device__ __forceinline__ void mma16816(float c[4],
    unsigned a0, unsigned a1, unsigned a2, unsigned a3,
    unsigned b0, unsigned b1)
{
    asm volatile(
        "mma.sync.aligned.m16n8k16.row.col.f32.bf16.bf16.f32 "
        "{%0,%1,%2,%3}, {%4,%5,%6,%7}, {%8,%9}, {%0,%1,%2,%3};"
        : "+f"(c[0]), "+f"(c[1]), "+f"(c[2]), "+f"(c[3])
        : "r"(a0), "r"(a1), "r"(a2), "r"(a3), "r"(b0), "r"(b1));
}

__device__ __forceinline__ void split4(float4 v, uint2& h, uint2& l) {
    __nv_bfloat16 h0 = __float2bfloat16(v.x), h1 = __float2bfloat16(v.y);
    __nv_bfloat16 h2 = __float2bfloat16(v.z), h3 = __float2bfloat16(v.w);
    float r0 = v.x - __bfloat162float(h0), r1 = v.y - __bfloat162float(h1);
    float r2 = v.z - __bfloat162float(h2), r3 = v.w - __bfloat162float(h3);
    __nv_bfloat16 l0 = __float2bfloat16(r0), l1 = __float2bfloat16(r1);
    __nv_bfloat16 l2 = __float2bfloat16(r2), l3 = __float2bfloat16(r3);
    h.x = ((unsigned)__bfloat16_as_ushort(h1) << 16) | __bfloat16_as_ushort(h0);
    h.y = ((unsigned)__bfloat16_as_ushort(h3) << 16) | __bfloat16_as_ushort(h2);
    l.x = ((unsigned)__bfloat16_as_ushort(l1) << 16) | __bfloat16_as_ushort(l0);
    l.y = ((unsigned)__bfloat16_as_ushort(l3) << 16) | __bfloat16_as_ushort(l2);
}

#define GRID_BAR()                                                        \
    do {                                                                  \
        __threadfence();                                                  \
        __syncthreads();                                                  \
        if (tid == 0) {                                                   \
            unsigned target = s_sense ^ 1u;                               \
            s_sense = target;                                             \
            unsigned aidx = atomicAdd(&g_bar_count, 1u);                  \
            if (aidx == (unsigned)(NB - 1)) {                             \
                g_bar_count = 0u;                                         \
                __threadfence();                                          \
                g_bar_sense = target;                                     \
            } else {                                                      \
                while (g_bar_sense != target) __nanosleep(64);            \
            }                                                             \
        }                                                                 \
        __syncthreads();                                                  \
        __threadfence();                                                  \
    } while (0)

// ---------------------------------------------------------------------------
// Tile job: acc[2][4][4] += A[128xK] @ B[32xK]^T with bf16 3-term compensation.
// A fp32 K-major (ldA). B: transB ? fp32 [K x n] row-major : fp32 [32 x K].
// Warp w owns rows w*32..w*32+31; fragment mapping per PTX m16n8k16.
// ---------------------------------------------------------------------------
__device__ __forceinline__ void run_tile_mma(
    const float* __restrict__ A, int ldA,
    const float* __restrict__ B, int ldB, bool transB,
    int K, char* gs, int tid, float acc[2][4][4])
{
    unsigned* AH = (unsigned*)(gs + OFF_AH);
    unsigned* AL = (unsigned*)(gs + OFF_AL);
    unsigned* BH = (unsigned*)(gs + OFF_BH);
    unsigned* BL = (unsigned*)(gs + OFF_BL);
    const int w = tid >> 5, lane = tid & 31;
    const int g = lane >> 2, tg = lane & 3;

    for (int k0 = 0; k0 < K; k0 += 64) {
        const int chunk = (K - k0 < 64) ? (K - k0) : 64;   // 64 or 16
        const int qs = (chunk == 64) ? 4 : 2;
        const int qm = (1 << qs) - 1;

        // ---- stage A: 128 x chunk fp32 -> bf16 hi/lo ----
        for (int idx = tid; idx < (128 << qs); idx += NTH) {
            const int r = idx >> qs, c4 = idx & qm;
            float4 v = *(const float4*)&A[r * ldA + k0 + c4 * 4];
            uint2 h, l; split4(v, h, l);
            ((uint2*)AH)[r * 18 + c4] = h;
            ((uint2*)AL)[r * 18 + c4] = l;
        }
        // ---- stage B: 32 x chunk ----
        if (!transB) {
            for (int idx = tid; idx < (32 << qs); idx += NTH) {
                const int r = idx >> qs, c4 = idx & qm;
                float4 v = *(const float4*)&B[r * ldB + k0 + c4 * 4];
                uint2 h, l; split4(v, h, l);
                ((uint2*)BH)[r * 18 + c4] = h;
                ((uint2*)BL)[r * 18 + c4] = l;
            }
        } else {
            for (int idx = tid; idx < (chunk << 3); idx += NTH) {
                const int k = idx >> 3, n4 = (idx & 7) * 4;
                float4 v = *(const float4*)&B[(k0 + k) * ldB + n4];
                float vv[4] = {v.x, v.y, v.z, v.w};
#pragma unroll
                for (int j = 0; j < 4; ++j) {
                    __nv_bfloat16 hh = __float2bfloat16(vv[j]);
                    float rr = vv[j] - __bfloat162float(hh);
                    __nv_bfloat16 ll = __float2bfloat16(rr);
                    const unsigned bo = (unsigned)((n4 + j) * 144 + k * 2);
                    *(unsigned short*)((char*)BH + bo) = __bfloat16_as_ushort(hh);
                    *(unsigned short*)((char*)BL + bo) = __bfloat16_as_ushort(ll);
                }
            }
        }
        __syncthreads();

        const int steps = chunk >> 4;
        for (int kk = 0; kk < steps; ++kk) {
            const int kc = kk * 8 + tg;
            unsigned ah[2][4], al[2][4];
#pragma unroll
            for (int i = 0; i < 2; ++i) {
                const int r0 = (w * 32 + i * 16 + g) * PITCHU;
                const int r1 = r0 + 8 * PITCHU;
                ah[i][0] = AH[r0 + kc];     ah[i][1] = AH[r1 + kc];
                ah[i][2] = AH[r0 + kc + 4]; ah[i][3] = AH[r1 + kc + 4];
                al[i][0] = AL[r0 + kc];     al[i][1] = AL[r1 + kc];
                al[i][2] = AL[r0 + kc + 4]; al[i][3] = AL[r1 + kc + 4];
            }
#pragma unroll
            for (int j = 0; j < 4; ++j) {
                const int nrow = (j * 8 + g) * PITCHU;
                const unsigned bh0 = BH[nrow + kc], bh1 = BH[nrow + kc + 4];
                const unsigned bl0 = BL[nrow + kc], bl1 = BL[nrow + kc + 4];
#pragma unroll
                for (int i = 0; i < 2; ++i) {
                    mma16816(acc[i][j], ah[i][0], ah[i][1], ah[i][2], ah[i][3], bh0, bh1);
                    mma16816(acc[i][j], ah[i][0], ah[i][1], ah[i][2], ah[i][3], bl0, bl1);
                    mma16816(acc[i][j], al[i][0], al[i][1], al[i][2], al[i][3], bh0, bh1);
                }
            }
        }
        __syncthreads();
    }
}

// epilogue: scatter acc to dst (fp32), optional bias and scale
__device__ __forceinline__ void epi_store(
    float acc[2][4][4], float* __restrict__ dst, int ldc, int m0, int n0,
    const float* __restrict__ bias, float scale, int tid)
{
    const int w = tid >> 5, lane = tid & 31;
    const int g = lane >> 2, tg = lane & 3;
#pragma unroll
    for (int i = 0; i < 2; ++i) {
        const int row0 = m0 + w * 32 + i * 16 + g;
#pragma unroll
        for (int j = 0; j < 4; ++j) {
            const int col = n0 + j * 8 + 2 * tg;
            const float b0 = bias ? bias[col] : 0.f;
            const float b1 = bias ? bias[col + 1] : 0.f;
            float2 v0 = make_float2(acc[i][j][0] * scale + b0,
                                    acc[i][j][1] * scale + b1);
            float2 v1 = make_float2(acc[i][j][2] * scale + b0,
                                    acc[i][j][3] * scale + b1);
            *(float2*)&dst[(size_t)row0 * ldc + col]       = v0;
            *(float2*)&dst[(size_t)(row0 + 8) * ldc + col] = v1;
        }
    }
}

// ---------------------------------------------------------------------------
__global__ __launch_bounds__(NTH)
void fused_kernel(const float* __restrict__ hid,   const float* __restrict__ act,
                  const int*   __restrict__ state,
                  const float* __restrict__ W_enc, const float* __restrict__ b_enc,
                  const float* __restrict__ Wq,  const float* __restrict__ bq,
                  const float* __restrict__ Wk,  const float* __restrict__ bk,
                  const float* __restrict__ Wv,  const float* __restrict__ bv,
                  const float* __restrict__ Wiq, const float* __restrict__ biq,
                  const float* __restrict__ Wik, const float* __restrict__ bik,
                  const float* __restrict__ Wiv, const float* __restrict__ biv,
                  const float* __restrict__ Wo,  const float* __restrict__ bo,
                  const float* __restrict__ W_O,
                  const float* __restrict__ W_val, const float* __restrict__ b_val,
                  const float* __restrict__ W_adv, const float* __restrict__ b_adv,
                  float* __restrict__ out)
{
    extern __shared__ char gs[];
    __shared__ unsigned s_sense;
    __shared__ int s_sn;

    const int tid = threadIdx.x;
    const int bx  = blockIdx.x;
    const int wid = tid >> 5, lane = tid & 31;
    if (tid == 0) s_sense = 0u;
    __syncthreads();

    // =====================================================================
    // PHASE 0: bx 0..15 obs-encode+action; 16..24 head combine; 25 mask
    // =====================================================================
    if (bx < 16) {
        const int base = bx * 16;
        const int ai   = base + (tid >> 3);
        const int tgrp = (tid & 7) * 2;
        float o0 = b_enc[tgrp], o1 = b_enc[tgrp + 1];
        for (int d = 0; d < HID; ++d) {
            const float hv = hid[ai * HID + d];
            o0 += hv * W_enc[d * 16 + tgrp];
            o1 += hv * W_enc[d * 16 + tgrp + 1];
        }
        g_C[ai * DD + tgrp]     = o0;
        g_C[ai * DD + tgrp + 1] = o1;
        const float4* act4 = (const float4*)act;
        for (int idx = tid; idx < 16 * 32; idx += NTH) {
            const int row = idx >> 5, col = idx & 31;
            *(float4*)&g_C[(base + row) * DD + 16 + col * 4] =
                act4[(base + row) * 32 + col];
        }
    } else if (bx < 25) {
        const int part = bx - 16;
        float* W2 = (float*)gs;    // 576*6 floats = 13824B
        for (int r = tid; r < EE; r += NTH) {
            float a[6] = {};
            for (int k = 0; k < DD; ++k) {
                const float w = W_O[r * DD + k];
                a[0] += w * W_val[k];
#pragma unroll
                for (int j = 0; j < ACT; ++j) a[1 + j] += w * W_adv[k * ACT + j];
            }
#pragma unroll
            for (int j = 0; j < 6; ++j) W2[r * 6 + j] = a[j];
        }
        __syncthreads();
        {
            const int e  = part * 64 + (tid >> 1);
            const int f0 = (tid & 1) * 288;
            float a[6] = {};
            for (int f = f0; f < f0 + 288; ++f) {
                const float w = Wo[e * EE + f];
#pragma unroll
                for (int j = 0; j < 6; ++j) a[j] += w * W2[f * 6 + j];
            }
#pragma unroll
            for (int j = 0; j < 6; ++j)
                a[j] += __shfl_xor_sync(0xffffffffu, a[j], 1);
            if (!(tid & 1)) {
#pragma unroll
                for (int j = 0; j < 6; ++j) g_Wfin[e * 6 + j] = a[j];
            }
        }
        if (part == 0 && tid < 6) {
            float s = 0.f;
            for (int f = 0; f < EE; ++f) s += bo[f] * W2[f * 6 + tid];
            g_bfin[tid] = s;
        }
    } else if (bx == 25) {
        int* px = (int*)gs; int* py = px + NA;
        for (int i = tid; i < NA; i += NTH) { px[i] = state[2 * i]; py[i] = state[2 * i + 1]; }
        __syncthreads();
        for (int i = tid; i < NA; i += NTH) {
            unsigned wbits[8] = {0, 0, 0, 0, 0, 0, 0, 0};
            const int xi = px[i], yi = py[i];
            for (int j = i + 1; j < NA; ++j) {
                const int dx = abs(xi - px[j]);
                const int dy = abs(yi - py[j]);
                if (dx <= OBS_RX && dy <= OBS_RY) wbits[j >> 5] |= (1u << (j & 31));
            }
#pragma unroll
            for (int t = 0; t < 8; ++t) g_mask[i * 8 + t] = wbits[t];
        }
    }
    GRID_BAR();

    // =====================================================================
    // PHASE B1: P(z) = C @ Wz + bz   (108 jobs: 3z x 2m x 18n, K=144)
    // =====================================================================
    if (bx < 108) {
        const int z  = bx / 36, r = bx % 36;
        const int m0 = (r / 18) * 128, n0 = (r % 18) * 32;
        const float* Wz = (z == 0) ? Wq : (z == 1) ? Wk : Wv;
        const float* bz = (z == 0) ? bq : (z == 1) ? bk : bv;
        float acc[2][4][4] = {};
        run_tile_mma(g_C + m0 * DD, DD, Wz + n0, EE, true, DD, gs, tid, acc);
        epi_store(acc, &g_P[z][0], EE, m0, n0 - 0, bz, 1.0f, tid);
        // note: epi col index = n0 + j*8 + 2tg; bias indexed at same col of the
        // 576-wide row, so pass dst base and bias base unshifted:
    }
    GRID_BAR();

    // =====================================================================
    // PHASE B2: qkv(z) = P(z) @ Wiz + biz   (108 jobs, K=576)
    // =====================================================================
    if (bx < 108) {
        const int z  = bx / 36, r = bx % 36;
        const int m0 = (r / 18) * 128, n0 = (r % 18) * 32;
        const float* Wiz = (z == 0) ? Wiq : (z == 1) ? Wik : Wiv;
        const float* biz = (z == 0) ? biq : (z == 1) ? bik : biv;
        float acc[2][4][4] = {};
        run_tile_mma(&g_P[z][0] + m0 * EE, EE, Wiz + n0, EE, true, EE, gs, tid, acc);
        epi_store(acc, &g_Q[z][0], EE, m0, n0, biz, 1.0f, tid);
    }
    GRID_BAR();

    // =====================================================================
    // PHASE S: S[h] = (1/12) q2_h @ k2_h^T  (64 jobs: 4h x 2m x 8n, K=144)
    // =====================================================================
    if (bx < 64) {
        const int h  = bx / 16, r = bx % 16;
        const int m0 = (r / 8) * 128, n0 = (r % 8) * 32;
        float acc[2][4][4] = {};
        run_tile_mma(&g_Q[0][0] + m0 * EE + h * HDH, EE,
                     &g_Q[1][0] + n0 * EE + h * HDH, EE, false, HDH,
                     gs, tid, acc);
        epi_store(acc, g_S + h * NA * NA, NA, m0, n0, nullptr, 1.0f / 12.0f, tid);
    }
    GRID_BAR();

    // =====================================================================
    // PHASE D: per-agent masked softmax-sum + sparse context -> G, cnt
    // =====================================================================
    {
        float* w  = (float*)gs;            // NH*NA floats = 4096B
        int*   Jl = (int*)(gs + 4096);     // NA ints
        for (int i = bx; i < NA; i += NB) {
            for (int t = tid; t < NH * NA; t += NTH) w[t] = 0.f;
            if (tid == 0) {
                int n = 0;
                for (int t = 0; t < 8; ++t) {
                    unsigned bits = g_mask[i * 8 + t];
                    while (bits) {
                        const int b = __ffs(bits) - 1;
                        Jl[n++] = t * 32 + b;
                        bits &= bits - 1;
                    }
                }
                s_sn = n;
                g_cnt[i] = (float)n;
            }
            __syncthreads();
            const int n = s_sn;
            if (n == 0) {
                for (int e = tid; e < EE; e += NTH) g_G[i * EE + e] = 0.f;
            } else {
                for (int p = tid; p < NH * n; p += NTH) {
                    const int h  = p & 3;
                    const int jj = Jl[p >> 2];
                    const float* row = g_S + h * NA * NA + jj * NA;
                    float m = -1e30f;
                    for (int t = 0; t < n; ++t) m = fmaxf(m, row[Jl[t]]);
                    float sum = 0.f;
                    for (int t = 0; t < n; ++t) sum += expf(row[Jl[t]] - m);
                    const float inv = 1.f / sum;
                    for (int t = 0; t < n; ++t)
                        atomicAdd(&w[h * NA + t], expf(row[Jl[t]] - m) * inv);
                }
                __syncthreads();
                const float* v2 = &g_Q[2][0];
                for (int e = tid; e < EE; e += NTH) {
                    const int h = e / HDH;
                    float acc = 0.f;
                    for (int t = 0; t < n; ++t)
                        acc += w[h * NA + t] * v2[Jl[t] * EE + e];
                    g_G[i * EE + e] = acc;
                }
            }
            __syncthreads();
        }
    }
    GRID_BAR();

    // =====================================================================
    // PHASE E: warp-per-agent final head (4 warps/CTA)
    // =====================================================================
    {
        const int gw = bx * 4 + wid;
        if (gw < NA) {
            const float* Gr = g_G + gw * EE;
            float a[6] = {};
            for (int d = lane; d < EE; d += 32) {
                const float gv = Gr[d];
                const float* Wr = g_Wfin + d * 6;
#pragma unroll
                for (int j = 0; j < 6; ++j) a[j] += gv * Wr[j];
            }
#pragma unroll
            for (int j = 0; j < 6; ++j)
#pragma unroll
                for (int o = 16; o > 0; o >>= 1)
                    a[j] += __shfl_xor_sync(0xffffffffu, a[j], o);
            const float c = g_cnt[gw];
            const float V = a[0] + c * g_bfin[0] + b_val[0];
            float A[ACT], mean = 0.f;
#pragma unroll
            for (int j = 0; j < ACT; ++j) {
                A[j] = a[1 + j] + c * g_bfin[1 + j] + b_adv[j];
                mean += A[j];
            }
            mean *= (1.f / ACT);
            if (lane < ACT) out[gw * ACT + lane] = V + A[lane] - mean;
        }
    }
    GRID_BAR();   // 6 barriers total: even sense-flip count per replay
}

// ---------------------------------------------------------------------------
extern "C" void kernel_launch(void* const* d_in, const int* in_sizes, int n_in,
                              void* d_out, int out_size)
{
    const float *hid, *act, *W_enc, *b_enc, *Wq, *bq, *Wk, *bk, *Wv, *bv;
    const float *Wiq, *biq, *Wik, *bik, *Wiv, *biv, *Wo, *bo, *W_O;
    const float *W_val, *b_val, *W_adv, *b_adv;
    const int* state;

    if (n_in >= 3 && in_sizes[2] == 512) {
        hid   = (const float*)d_in[0];  act  = (const float*)d_in[1];
        state = (const int*)  d_in[2];
        W_enc = (const float*)d_in[3];  b_enc = (const float*)d_in[4];
        Wq  = (const float*)d_in[5];    bq  = (const float*)d_in[6];
        Wk  = (const float*)d_in[7];    bk  = (const float*)d_in[8];
        Wv  = (const float*)d_in[9];    bv  = (const float*)d_in[10];
        Wiq = (const float*)d_in[11];   biq = (const float*)d_in[12];
        Wik = (const float*)d_in[13];   bik = (const float*)d_in[14];
        Wiv = (const float*)d_in[15];   biv = (const float*)d_in[16];
        Wo  = (const float*)d_in[17];   bo  = (const float*)d_in[18];
        W_O = (const float*)d_in[19];
        W_val = (const float*)d_in[20]; b_val = (const float*)d_in[21];
        W_adv = (const float*)d_in[22]; b_adv = (const float*)d_in[23];
    } else {
        hid   = (const float*)d_in[0];  act  = (const float*)d_in[1];
        W_enc = (const float*)d_in[2];  b_enc = (const float*)d_in[3];
        Wq  = (const float*)d_in[4];    bq  = (const float*)d_in[5];
        Wk  = (const float*)d_in[6];    bk  = (const float*)d_in[7];
        Wv  = (const float*)d_in[8];    bv  = (const float*)d_in[9];
        Wiq = (const float*)d_in[10];   biq = (const float*)d_in[11];
        Wik = (const float*)d_in[12];   bik = (const float*)d_in[13];
        Wiv = (const float*)d_in[14];   biv = (const float*)d_in[15];
        Wo  = (const float*)d_in[16];   bo  = (const float*)d_in[17];
        W_O = (const float*)d_in[18];
        W_val = (const float*)d_in[19]; b_val = (const float*)d_in[20];
        W_adv = (const float*)d_in[21]; b_adv = (const float*)d_in[22];
        state = (const int*)  d_in[23];
    }

    static bool attr_set = false;
    if (!attr_set) {
        cudaFuncSetAttribute(fused_kernel,
                             cudaFuncAttributeMaxDynamicSharedMemorySize, SMEM_DYN);
        attr_set = true;
    }

    fused_kernel<<<NB, NTH, SMEM_DYN>>>(hid, act, state, W_enc, b_enc,
                                        Wq, bq, Wk, bk, Wv, bv,
                                        Wiq, biq, Wik, bik, Wiv, biv,
                                        Wo, bo, W_O, W_val, b_val, W_adv, b_adv,
                                        (float*)d_out);
}

// round 9
// speedup vs baseline: 1.2557x; 1.2557x over previous
#include <cuda_runtime.h>
#include <cuda_bf16.h>
#include <math.h>
#include <stdint.h>

typedef unsigned short ushortt;

// ---------------------------------------------------------------------------
#define NA   256
#define HID  128
#define ACT  5
#define NH   4
#define DD   144
#define EE   576
#define HDH  144
#define OBS_RX 4
#define OBS_RY 2
#define NB   148
#define NTH  256

// GEMM smem: chunk K=48 bf16 -> 96B rows padded to 112B (28 uints, conflict-free)
#define PITCHU 28
#define CHUNK  48
#define A_BYTES (128 * 112)            // 14336
#define B_BYTES (64 * 112)             // 7168
#define OFF_AL  14336
#define OFF_BH  28672
#define OFF_BL  35840
#define BUF_BYTES 43008
#define SMEM_DYN  (2 * BUF_BYTES)      // 86016

// ---------------------------------------------------------------------------
__device__ ushortt  g_Cb[2][NA * DD];            // C bf16 hi/lo
__device__ ushortt  g_Wzb[2][3][EE * DD];        // Wq/Wk/Wv transposed [n][k]
__device__ ushortt  g_Wib[2][3][EE * EE];        // Wiq/Wik/Wiv transposed [n][k]
__device__ ushortt  g_Pb[2][3][NA * EE];         // P bf16 hi/lo
__device__ ushortt  g_Qb[2][2][NA * EE];         // q,k bf16 hi/lo
__device__ __align__(16) float g_Qv[NA * EE];    // v fp32
__device__ __align__(16) float g_S[NH * NA * NA];
__device__ unsigned g_mask[NA * 8];
__device__ __align__(16) float g_G[NA * EE];
__device__ float    g_cnt[NA];
__device__ __align__(16) float g_Wfin[EE * 6];
__device__ float    g_bfin[6];
__device__ unsigned          g_bar_count;
__device__ volatile unsigned g_bar_sense;

// ---------------------------------------------------------------------------
__device__ __forceinline__ unsigned su32(const void* p) {
    unsigned a;
    asm("{ .reg .u64 t; cvta.to.shared.u64 t, %1; cvt.u32.u64 %0, t; }"
        : "=r"(a) : "l"(p));
    return a;
}
__device__ __forceinline__ void cpa16(unsigned s, const void* g) {
    asm volatile("cp.async.cg.shared.global [%0], [%1], 16;" :: "r"(s), "l"(g));
}
#define CPA_COMMIT() asm volatile("cp.async.commit_group;" ::: "memory")
#define CPA_WAIT0()  asm volatile("cp.async.wait_group 0;" ::: "memory")

__device__ __forceinline__ void mma16816(float c[4],
    unsigned a0, unsigned a1, unsigned a2, unsigned a3,
    unsigned b0, unsigned b1)
{
    asm volatile(
        "mma.sync.aligned.m16n8k16.row.col.f32.bf16.bf16.f32 "
        "{%0,%1,%2,%3}, {%4,%5,%6,%7}, {%8,%9}, {%0,%1,%2,%3};"
        : "+f"(c[0]), "+f"(c[1]), "+f"(c[2]), "+f"(c[3])
        : "r"(a0), "r"(a1), "r"(a2), "r"(a3), "r"(b0), "r"(b1));
}

__device__ __forceinline__ void split1(float v, ushortt& h, ushortt& l) {
    __nv_bfloat16 hb = __float2bfloat16(v);
    float r = v - __bfloat162float(hb);
    __nv_bfloat16 lb = __float2bfloat16(r);
    h = __bfloat16_as_ushort(hb);
    l = __bfloat16_as_ushort(lb);
}
__device__ __forceinline__ void split2(float v0, float v1, unsigned& h, unsigned& l) {
    ushortt h0, l0, h1, l1;
    split1(v0, h0, l0); split1(v1, h1, l1);
    h = ((unsigned)h1 << 16) | h0;
    l = ((unsigned)l1 << 16) | l0;
}

#define GRID_BAR()                                                        \
    do {                                                                  \
        __threadfence();                                                  \
        __syncthreads();                                                  \
        if (tid == 0) {                                                   \
            unsigned target = s_sense ^ 1u;                               \
            s_sense = target;                                             \
            unsigned aidx = atomicAdd(&g_bar_count, 1u);                  \
            if (aidx == (unsigned)(NB - 1)) {                             \
                g_bar_count = 0u;                                         \
                __threadfence();                                          \
                g_bar_sense = target;                                     \
            } else {                                                      \
                while (g_bar_sense != target) __nanosleep(64);            \
            }                                                             \
        }                                                                 \
        __syncthreads();                                                  \
        __threadfence();                                                  \
    } while (0)

// ---------------------------------------------------------------------------
// stage one K=48 chunk via cp.async: A(128 rows), B(64 rows) hi+lo
// ---------------------------------------------------------------------------
__device__ __forceinline__ void stage_chunk(
    const ushortt* __restrict__ AH, const ushortt* __restrict__ AL, int lda,
    const ushortt* __restrict__ BH, const ushortt* __restrict__ BL, int ldb,
    int k0, unsigned sbuf, int tid)
{
    for (int idx = tid; idx < 768; idx += NTH) {
        const int r = idx / 6, c = idx % 6;
        const unsigned d = sbuf + r * 112 + c * 16;
        const int go = r * lda + k0 + c * 8;
        cpa16(d,          AH + go);
        cpa16(d + OFF_AL, AL + go);
    }
    for (int idx = tid; idx < 384; idx += NTH) {
        const int r = idx / 6, c = idx % 6;
        const unsigned d = sbuf + OFF_BH + r * 112 + c * 16;
        const int go = r * ldb + k0 + c * 8;
        cpa16(d,                     BH + go);
        cpa16(d + (OFF_BL - OFF_BH), BL + go);
    }
}

// one K=48 chunk of MMAs (3 kk-steps, 3-term compensation)
__device__ __forceinline__ void mma_chunk(const char* buf, int wm, int wn,
                                          int g, int tg, float acc[2][4][4])
{
    const unsigned* AH = (const unsigned*)buf;
    const unsigned* AL = (const unsigned*)(buf + OFF_AL);
    const unsigned* BH = (const unsigned*)(buf + OFF_BH);
    const unsigned* BL = (const unsigned*)(buf + OFF_BL);
#pragma unroll
    for (int kk = 0; kk < 3; ++kk) {
        const int kc = kk * 8 + tg;
        unsigned ah[2][4], al[2][4];
#pragma unroll
        for (int i = 0; i < 2; ++i) {
            const int r0 = (wm * 32 + i * 16 + g) * PITCHU;
            const int r1 = r0 + 8 * PITCHU;
            ah[i][0] = AH[r0 + kc];     ah[i][1] = AH[r1 + kc];
            ah[i][2] = AH[r0 + kc + 4]; ah[i][3] = AH[r1 + kc + 4];
            al[i][0] = AL[r0 + kc];     al[i][1] = AL[r1 + kc];
            al[i][2] = AL[r0 + kc + 4]; al[i][3] = AL[r1 + kc + 4];
        }
#pragma unroll
        for (int j = 0; j < 4; ++j) {
            const int nrow = (wn * 32 + j * 8 + g) * PITCHU;
            const unsigned bh0 = BH[nrow + kc], bh1 = BH[nrow + kc + 4];
            const unsigned bl0 = BL[nrow + kc], bl1 = BL[nrow + kc + 4];
#pragma unroll
            for (int i = 0; i < 2; ++i) {
                mma16816(acc[i][j], ah[i][0], ah[i][1], ah[i][2], ah[i][3], bh0, bh1);
                mma16816(acc[i][j], ah[i][0], ah[i][1], ah[i][2], ah[i][3], bl0, bl1);
                mma16816(acc[i][j], al[i][0], al[i][1], al[i][2], al[i][3], bh0, bh1);
            }
        }
    }
}

// double-buffered tile: acc = A[128xK] @ B[64xK]^T (bf16 hi/lo inputs)
__device__ __forceinline__ void run_tile(
    const ushortt* AH, const ushortt* AL, int lda,
    const ushortt* BH, const ushortt* BL, int ldb,
    int K, char* gs, unsigned gs_u32, int tid, float acc[2][4][4])
{
    const int nc = K / CHUNK;
    stage_chunk(AH, AL, lda, BH, BL, ldb, 0, gs_u32, tid);
    CPA_COMMIT();
    for (int c = 0; c < nc; ++c) {
        CPA_WAIT0();
        __syncthreads();
        if (c + 1 < nc) {
            stage_chunk(AH, AL, lda, BH, BL, ldb, (c + 1) * CHUNK,
                        gs_u32 + ((c + 1) & 1) * BUF_BYTES, tid);
            CPA_COMMIT();
        }
        mma_chunk(gs + (c & 1) * BUF_BYTES, (tid >> 5) & 3, tid >> 7,
                  (tid & 31) >> 2, tid & 3, acc);
    }
    __syncthreads();
}

// ---------------------------------------------------------------------------
__global__ __launch_bounds__(NTH)
void fused_kernel(const float* __restrict__ hid,   const float* __restrict__ act,
                  const int*   __restrict__ state,
                  const float* __restrict__ W_enc, const float* __restrict__ b_enc,
                  const float* __restrict__ Wq,  const float* __restrict__ bq,
                  const float* __restrict__ Wk,  const float* __restrict__ bk,
                  const float* __restrict__ Wv,  const float* __restrict__ bv,
                  const float* __restrict__ Wiq, const float* __restrict__ biq,
                  const float* __restrict__ Wik, const float* __restrict__ bik,
                  const float* __restrict__ Wiv, const float* __restrict__ biv,
                  const float* __restrict__ Wo,  const float* __restrict__ bo,
                  const float* __restrict__ W_O,
                  const float* __restrict__ W_val, const float* __restrict__ b_val,
                  const float* __restrict__ W_adv, const float* __restrict__ b_adv,
                  float* __restrict__ out)
{
    extern __shared__ char gs[];
    __shared__ unsigned s_sense;
    __shared__ int s_sn;

    const int tid = threadIdx.x;
    const int bx  = blockIdx.x;
    const int wid = tid >> 5, lane = tid & 31;
    const int wm = wid & 3, wn = wid >> 2;
    const int g = lane >> 2, tg = lane & 3;
    const unsigned gs_u32 = su32(gs);
    if (tid == 0) s_sense = 0u;
    __syncthreads();

    // =====================================================================
    // PHASE 0 (static pool, 3 rounds):
    //   0..15   obs encode + action -> g_Cb (bf16 hi/lo)
    //   16..96  transpose+convert Wq/Wk/Wv -> g_Wzb  (81 jobs of 48k x 64n)
    //   97..420 transpose+convert Wiq/Wik/Wiv -> g_Wib (324 jobs)
    //   421..429 head combine
    //   430     visibility mask
    // =====================================================================
    for (int t = 0; t < 3; ++t) {
        const int job = bx + t * NB;
        if (job < 16) {
            const int base = job * 16;
            {   // encoder cols: 16 threads per agent, 1 col each
                const int ai = base + (tid >> 4);
                const int c  = tid & 15;
                float o = b_enc[c];
                for (int d = 0; d < HID; ++d)
                    o += hid[ai * HID + d] * W_enc[d * 16 + c];
                ushortt h, l; split1(o, h, l);
                g_Cb[0][ai * DD + c] = h;
                g_Cb[1][ai * DD + c] = l;
            }
            for (int idx = tid; idx < 16 * 128; idx += NTH) {
                const int ai = base + (idx >> 7), col = idx & 127;
                ushortt h, l; split1(act[ai * HID + col], h, l);
                g_Cb[0][ai * DD + 16 + col] = h;
                g_Cb[1][ai * DD + 16 + col] = l;
            }
        } else if (job < 97) {
            const int jz = job - 16;
            const int z = jz / 27, rem = jz % 27;
            const int kb = (rem / 9) * 48, nb = (rem % 9) * 64;
            const float* src = (z == 0) ? Wq : (z == 1) ? Wk : Wv;   // [144][576]
            float* T = (float*)gs;      // [48][65]
            for (int idx = tid; idx < 768; idx += NTH) {
                const int r = idx >> 4, c4 = (idx & 15) * 4;
                float4 v = *(const float4*)&src[(kb + r) * EE + nb + c4];
                T[r * 65 + c4 + 0] = v.x; T[r * 65 + c4 + 1] = v.y;
                T[r * 65 + c4 + 2] = v.z; T[r * 65 + c4 + 3] = v.w;
            }
            __syncthreads();
            for (int idx = tid; idx < 3072; idx += NTH) {
                const int n = idx / 48, k = idx % 48;
                ushortt h, l; split1(T[k * 65 + n], h, l);
                const int o = (nb + n) * DD + kb + k;
                g_Wzb[0][z][o] = h; g_Wzb[1][z][o] = l;
            }
        } else if (job < 421) {
            const int jw = job - 97;
            const int z = jw / 108, rem = jw % 108;
            const int kb = (rem / 9) * 48, nb = (rem % 9) * 64;
            const float* src = (z == 0) ? Wiq : (z == 1) ? Wik : Wiv;  // [576][576]
            float* T = (float*)gs;
            for (int idx = tid; idx < 768; idx += NTH) {
                const int r = idx >> 4, c4 = (idx & 15) * 4;
                float4 v = *(const float4*)&src[(kb + r) * EE + nb + c4];
                T[r * 65 + c4 + 0] = v.x; T[r * 65 + c4 + 1] = v.y;
                T[r * 65 + c4 + 2] = v.z; T[r * 65 + c4 + 3] = v.w;
            }
            __syncthreads();
            for (int idx = tid; idx < 3072; idx += NTH) {
                const int n = idx / 48, k = idx % 48;
                ushortt h, l; split1(T[k * 65 + n], h, l);
                const int o = (nb + n) * EE + kb + k;
                g_Wib[0][z][o] = h; g_Wib[1][z][o] = l;
            }
        } else if (job < 430) {
            const int part = job - 421;
            float* W2 = (float*)gs;   // 576*6
            for (int r = tid; r < EE; r += NTH) {
                float a[6] = {};
                for (int k = 0; k < DD; ++k) {
                    const float w = W_O[r * DD + k];
                    a[0] += w * W_val[k];
#pragma unroll
                    for (int j = 0; j < ACT; ++j) a[1 + j] += w * W_adv[k * ACT + j];
                }
#pragma unroll
                for (int j = 0; j < 6; ++j) W2[r * 6 + j] = a[j];
            }
            __syncthreads();
            {
                const int e  = part * 64 + (tid >> 2);
                const int f0 = (tid & 3) * 144;
                float a[6] = {};
                for (int f = f0; f < f0 + 144; ++f) {
                    const float w = Wo[e * EE + f];
#pragma unroll
                    for (int j = 0; j < 6; ++j) a[j] += w * W2[f * 6 + j];
                }
#pragma unroll
                for (int j = 0; j < 6; ++j) {
                    a[j] += __shfl_xor_sync(0xffffffffu, a[j], 1);
                    a[j] += __shfl_xor_sync(0xffffffffu, a[j], 2);
                }
                if ((tid & 3) == 0) {
#pragma unroll
                    for (int j = 0; j < 6; ++j) g_Wfin[e * 6 + j] = a[j];
                }
            }
            if (part == 0 && tid < 6) {
                float s = 0.f;
                for (int f = 0; f < EE; ++f) s += bo[f] * W2[f * 6 + tid];
                g_bfin[tid] = s;
            }
        } else if (job == 430) {
            int* px = (int*)gs; int* py = px + NA;
            px[tid] = state[2 * tid]; py[tid] = state[2 * tid + 1];
            __syncthreads();
            unsigned wb[8] = {0, 0, 0, 0, 0, 0, 0, 0};
            const int xi = px[tid], yi = py[tid];
            for (int j = tid + 1; j < NA; ++j) {
                const int dx = abs(xi - px[j]);
                const int dy = abs(yi - py[j]);
                if (dx <= OBS_RX && dy <= OBS_RY) wb[j >> 5] |= (1u << (j & 31));
            }
#pragma unroll
            for (int q = 0; q < 8; ++q) g_mask[tid * 8 + q] = wb[q];
        }
        __syncthreads();
    }
    GRID_BAR();

    // =====================================================================
    // PHASE B1: P(z) = C @ Wz + bz   (54 jobs: 3z x 2m x 9n, K=144)
    // =====================================================================
    if (bx < 54) {
        const int z  = bx / 18, r = bx % 18;
        const int m0 = (r / 9) * 128, n0 = (r % 9) * 64;
        const float* bz = (z == 0) ? bq : (z == 1) ? bk : bv;
        float acc[2][4][4] = {};
        run_tile(&g_Cb[0][0] + m0 * DD, &g_Cb[1][0] + m0 * DD, DD,
                 &g_Wzb[0][z][0] + n0 * DD, &g_Wzb[1][z][0] + n0 * DD, DD,
                 DD, gs, gs_u32, tid, acc);
#pragma unroll
        for (int i = 0; i < 2; ++i) {
            const int row = m0 + wm * 32 + i * 16 + g;
#pragma unroll
            for (int j = 0; j < 4; ++j) {
                const int col = n0 + wn * 32 + j * 8 + 2 * tg;
                const float b0 = bz[col], b1 = bz[col + 1];
                unsigned h, l;
                split2(acc[i][j][0] + b0, acc[i][j][1] + b1, h, l);
                *(unsigned*)&g_Pb[0][z][row * EE + col] = h;
                *(unsigned*)&g_Pb[1][z][row * EE + col] = l;
                split2(acc[i][j][2] + b0, acc[i][j][3] + b1, h, l);
                *(unsigned*)&g_Pb[0][z][(row + 8) * EE + col] = h;
                *(unsigned*)&g_Pb[1][z][(row + 8) * EE + col] = l;
            }
        }
    }
    GRID_BAR();

    // =====================================================================
    // PHASE B2: qkv(z) = P(z) @ Wiz + biz   (54 jobs, K=576)
    // =====================================================================
    if (bx < 54) {
        const int z  = bx / 18, r = bx % 18;
        const int m0 = (r / 9) * 128, n0 = (r % 9) * 64;
        const float* biz = (z == 0) ? biq : (z == 1) ? bik : biv;
        float acc[2][4][4] = {};
        run_tile(&g_Pb[0][z][0] + m0 * EE, &g_Pb[1][z][0] + m0 * EE, EE,
                 &g_Wib[0][z][0] + n0 * EE, &g_Wib[1][z][0] + n0 * EE, EE,
                 EE, gs, gs_u32, tid, acc);
#pragma unroll
        for (int i = 0; i < 2; ++i) {
            const int row = m0 + wm * 32 + i * 16 + g;
#pragma unroll
            for (int j = 0; j < 4; ++j) {
                const int col = n0 + wn * 32 + j * 8 + 2 * tg;
                const float b0 = biz[col], b1 = biz[col + 1];
                const float v0 = acc[i][j][0] + b0, v1 = acc[i][j][1] + b1;
                const float v2 = acc[i][j][2] + b0, v3 = acc[i][j][3] + b1;
                if (z < 2) {
                    unsigned h, l;
                    split2(v0, v1, h, l);
                    *(unsigned*)&g_Qb[0][z][row * EE + col] = h;
                    *(unsigned*)&g_Qb[1][z][row * EE + col] = l;
                    split2(v2, v3, h, l);
                    *(unsigned*)&g_Qb[0][z][(row + 8) * EE + col] = h;
                    *(unsigned*)&g_Qb[1][z][(row + 8) * EE + col] = l;
                } else {
                    *(float2*)&g_Qv[row * EE + col]       = make_float2(v0, v1);
                    *(float2*)&g_Qv[(row + 8) * EE + col] = make_float2(v2, v3);
                }
            }
        }
    }
    GRID_BAR();

    // =====================================================================
    // PHASE S: S[h] = (1/12) q2_h @ k2_h^T  (32 jobs: 4h x 2m x 4n, K=144)
    // =====================================================================
    if (bx < 32) {
        const int h  = bx / 8, r = bx % 8;
        const int m0 = (r / 4) * 128, n0 = (r % 4) * 64;
        float acc[2][4][4] = {};
        run_tile(&g_Qb[0][0][0] + m0 * EE + h * HDH, &g_Qb[1][0][0] + m0 * EE + h * HDH, EE,
                 &g_Qb[0][1][0] + n0 * EE + h * HDH, &g_Qb[1][1][0] + n0 * EE + h * HDH, EE,
                 HDH, gs, gs_u32, tid, acc);
        float* Cd = g_S + h * NA * NA;
#pragma unroll
        for (int i = 0; i < 2; ++i) {
            const int row = m0 + wm * 32 + i * 16 + g;
#pragma unroll
            for (int j = 0; j < 4; ++j) {
                const int col = n0 + wn * 32 + j * 8 + 2 * tg;
                *(float2*)&Cd[row * NA + col] =
                    make_float2(acc[i][j][0] * (1.f / 12.f), acc[i][j][1] * (1.f / 12.f));
                *(float2*)&Cd[(row + 8) * NA + col] =
                    make_float2(acc[i][j][2] * (1.f / 12.f), acc[i][j][3] * (1.f / 12.f));
            }
        }
    }
    GRID_BAR();

    // =====================================================================
    // PHASE D: per-agent masked softmax-sum + sparse context -> G, cnt
    // =====================================================================
    {
        float* w  = (float*)gs;            // NH*NA floats
        int*   Jl = (int*)(gs + 4096);     // NA ints
        for (int i = bx; i < NA; i += NB) {
            for (int q = tid; q < NH * NA; q += NTH) w[q] = 0.f;
            if (tid == 0) {
                int n = 0;
                for (int q = 0; q < 8; ++q) {
                    unsigned bits = g_mask[i * 8 + q];
                    while (bits) {
                        const int b = __ffs(bits) - 1;
                        Jl[n++] = q * 32 + b;
                        bits &= bits - 1;
                    }
                }
                s_sn = n;
                g_cnt[i] = (float)n;
            }
            __syncthreads();
            const int n = s_sn;
            if (n == 0) {
                for (int e = tid; e < EE; e += NTH) g_G[i * EE + e] = 0.f;
            } else {
                for (int p = tid; p < NH * n; p += NTH) {
                    const int h  = p & 3;
                    const int jj = Jl[p >> 2];
                    const float* row = g_S + h * NA * NA + jj * NA;
                    float m = -1e30f;
                    for (int q = 0; q < n; ++q) m = fmaxf(m, row[Jl[q]]);
                    float sum = 0.f;
                    for (int q = 0; q < n; ++q) sum += expf(row[Jl[q]] - m);
                    const float inv = 1.f / sum;
                    for (int q = 0; q < n; ++q)
                        atomicAdd(&w[h * NA + q], expf(row[Jl[q]] - m) * inv);
                }
                __syncthreads();
                for (int e = tid; e < EE; e += NTH) {
                    const int h = e / HDH;
                    float acc = 0.f;
                    for (int q = 0; q < n; ++q)
                        acc += w[h * NA + q] * g_Qv[Jl[q] * EE + e];
                    g_G[i * EE + e] = acc;
                }
            }
            __syncthreads();
        }
    }
    GRID_BAR();

    // =====================================================================
    // PHASE E: warp-per-agent final head (8 warps/CTA)
    // =====================================================================
    {
        const int gw = bx * 8 + wid;
        if (gw < NA) {
            const float* Gr = g_G + gw * EE;
            float a[6] = {};
            for (int d = lane; d < EE; d += 32) {
                const float gv = Gr[d];
                const float* Wr = g_Wfin + d * 6;
#pragma unroll
                for (int j = 0; j < 6; ++j) a[j] += gv * Wr[j];
            }
#pragma unroll
            for (int j = 0; j < 6; ++j)
#pragma unroll
                for (int o = 16; o > 0; o >>= 1)
                    a[j] += __shfl_xor_sync(0xffffffffu, a[j], o);
            const float c = g_cnt[gw];
            const float V = a[0] + c * g_bfin[0] + b_val[0];
            float A[ACT], mean = 0.f;
#pragma unroll
            for (int j = 0; j < ACT; ++j) {
                A[j] = a[1 + j] + c * g_bfin[1 + j] + b_adv[j];
                mean += A[j];
            }
            mean *= (1.f / ACT);
            if (lane < ACT) out[gw * ACT + lane] = V + A[lane] - mean;
        }
    }
    GRID_BAR();   // 6 barriers: even per replay
}

// ---------------------------------------------------------------------------
extern "C" void kernel_launch(void* const* d_in, const int* in_sizes, int n_in,
                              void* d_out, int out_size)
{
    const float *hid, *act, *W_enc, *b_enc, *Wq, *bq, *Wk, *bk, *Wv, *bv;
    const float *Wiq, *biq, *Wik, *bik, *Wiv, *biv, *Wo, *bo, *W_O;
    const float *W_val, *b_val, *W_adv, *b_adv;
    const int* state;

    if (n_in >= 3 && in_sizes[2] == 512) {
        hid   = (const float*)d_in[0];  act  = (const float*)d_in[1];
        state = (const int*)  d_in[2];
        W_enc = (const float*)d_in[3];  b_enc = (const float*)d_in[4];
        Wq  = (const float*)d_in[5];    bq  = (const float*)d_in[6];
        Wk  = (const float*)d_in[7];    bk  = (const float*)d_in[8];
        Wv  = (const float*)d_in[9];    bv  = (const float*)d_in[10];
        Wiq = (const float*)d_in[11];   biq = (const float*)d_in[12];
        Wik = (const float*)d_in[13];   bik = (const float*)d_in[14];
        Wiv = (const float*)d_in[15];   biv = (const float*)d_in[16];
        Wo  = (const float*)d_in[17];   bo  = (const float*)d_in[18];
        W_O = (const float*)d_in[19];
        W_val = (const float*)d_in[20]; b_val = (const float*)d_in[21];
        W_adv = (const float*)d_in[22]; b_adv = (const float*)d_in[23];
    } else {
        hid   = (const float*)d_in[0];  act  = (const float*)d_in[1];
        W_enc = (const float*)d_in[2];  b_enc = (const float*)d_in[3];
        Wq  = (const float*)d_in[4];    bq  = (const float*)d_in[5];
        Wk  = (const float*)d_in[6];    bk  = (const float*)d_in[7];
        Wv  = (const float*)d_in[8];    bv  = (const float*)d_in[9];
        Wiq = (const float*)d_in[10];   biq = (const float*)d_in[11];
        Wik = (const float*)d_in[12];   bik = (const float*)d_in[13];
        Wiv = (const float*)d_in[14];   biv = (const float*)d_in[15];
        Wo  = (const float*)d_in[16];   bo  = (const float*)d_in[17];
        W_O = (const float*)d_in[18];
        W_val = (const float*)d_in[19]; b_val = (const float*)d_in[20];
        W_adv = (const float*)d_in[21]; b_adv = (const float*)d_in[22];
        state = (const int*)  d_in[23];
    }

    static bool attr_set = false;
    if (!attr_set) {
        cudaFuncSetAttribute(fused_kernel,
                             cudaFuncAttributeMaxDynamicSharedMemorySize, SMEM_DYN);
        attr_set = true;
    }

    fused_kernel<<<NB, NTH, SMEM_DYN>>>(hid, act, state, W_enc, b_enc,
                                        Wq, bq, Wk, bk, Wv, bv,
                                        Wiq, biq, Wik, bik, Wiv, biv,
                                        Wo, bo, W_O, W_val, b_val, W_adv, b_adv,
                                        (float*)d_out);
}

// round 10
// speedup vs baseline: 1.3389x; 1.0663x over previous
#include <cuda_runtime.h>
#include <cuda_bf16.h>
#include <math.h>
#include <stdint.h>

typedef unsigned short ushortt;

// ---------------------------------------------------------------------------
#define NA   256
#define HID  128
#define ACT  5
#define NH   4
#define DD   144
#define EE   576
#define HDH  144
#define OBS_RX 4
#define OBS_RY 2
#define NB   148
#define NTH  256

// GEMM smem per stage: A hi/lo [128][48] bf16 pitch 112B; B either
//   mode-a: [64][48] bf16 pitch 112B (hi/lo)   (activations, direct-LDS frags)
//   mode-b: [48][64] bf16 pitch 144B (hi/lo)   (weights, ldmatrix.trans frags)
#define PITCHU 28          // A/mode-a row pitch in u32 (112B)
#define BPITCH 144         // mode-b row pitch bytes
#define CHUNK  48
#define OFF_AL 14336
#define OFF_BH 28672
#define OFF_BL 35840
#define BUF_BYTES 43008
#define SMEM_DYN  (2 * BUF_BYTES)   // 86016

// ---------------------------------------------------------------------------
__device__ __align__(16) ushortt g_Cb[2][NA * DD];     // C bf16 hi/lo [m][k]
__device__ __align__(16) ushortt g_Pb[2][3][NA * EE];  // P bf16 hi/lo
__device__ __align__(16) ushortt g_Qb[2][2][NA * EE];  // q,k bf16 hi/lo
__device__ __align__(16) float   g_Qv[NA * EE];        // v fp32
__device__ __align__(16) float   g_S[NH * NA * NA];
__device__ unsigned g_mask[NA * 8];
__device__ __align__(16) float   g_Wfin[EE * 6];
__device__ float    g_bfin[6];
__device__ unsigned          g_bar_count;
__device__ volatile unsigned g_bar_sense;

// ---------------------------------------------------------------------------
__device__ __forceinline__ unsigned su32(const void* p) {
    unsigned a;
    asm("{ .reg .u64 t; cvta.to.shared.u64 t, %1; cvt.u32.u64 %0, t; }"
        : "=r"(a) : "l"(p));
    return a;
}
__device__ __forceinline__ void cpa16(unsigned s, const void* g) {
    asm volatile("cp.async.cg.shared.global [%0], [%1], 16;" :: "r"(s), "l"(g));
}
#define CPA_COMMIT() asm volatile("cp.async.commit_group;" ::: "memory")
#define CPA_WAIT0()  asm volatile("cp.async.wait_group 0;" ::: "memory")

__device__ __forceinline__ void mma16816(float c[4],
    unsigned a0, unsigned a1, unsigned a2, unsigned a3,
    unsigned b0, unsigned b1)
{
    asm volatile(
        "mma.sync.aligned.m16n8k16.row.col.f32.bf16.bf16.f32 "
        "{%0,%1,%2,%3}, {%4,%5,%6,%7}, {%8,%9}, {%0,%1,%2,%3};"
        : "+f"(c[0]), "+f"(c[1]), "+f"(c[2]), "+f"(c[3])
        : "r"(a0), "r"(a1), "r"(a2), "r"(a3), "r"(b0), "r"(b1));
}
__device__ __forceinline__ void ldmx4t(unsigned& r0, unsigned& r1,
                                       unsigned& r2, unsigned& r3, unsigned a)
{
    asm volatile("ldmatrix.sync.aligned.m8n8.x4.trans.shared.b16 {%0,%1,%2,%3}, [%4];"
                 : "=r"(r0), "=r"(r1), "=r"(r2), "=r"(r3) : "r"(a));
}

__device__ __forceinline__ void split1(float v, ushortt& h, ushortt& l) {
    __nv_bfloat16 hb = __float2bfloat16(v);
    float r = v - __bfloat162float(hb);
    __nv_bfloat16 lb = __float2bfloat16(r);
    h = __bfloat16_as_ushort(hb);
    l = __bfloat16_as_ushort(lb);
}
__device__ __forceinline__ void split2(float v0, float v1, unsigned& h, unsigned& l) {
    ushortt h0, l0, h1, l1;
    split1(v0, h0, l0); split1(v1, h1, l1);
    h = ((unsigned)h1 << 16) | h0;
    l = ((unsigned)l1 << 16) | l0;
}

#define GRID_BAR()                                                        \
    do {                                                                  \
        __threadfence();                                                  \
        __syncthreads();                                                  \
        if (tid == 0) {                                                   \
            unsigned target = s_sense ^ 1u;                               \
            s_sense = target;                                             \
            unsigned aidx = atomicAdd(&g_bar_count, 1u);                  \
            if (aidx == (unsigned)(NB - 1)) {                             \
                g_bar_count = 0u;                                         \
                __threadfence();                                          \
                g_bar_sense = target;                                     \
            } else {                                                      \
                while (g_bar_sense != target) __nanosleep(64);            \
            }                                                             \
        }                                                                 \
        __syncthreads();                                                  \
        __threadfence();                                                  \
    } while (0)

// ---------------------------------------------------------------------------
// A staging via cp.async: 128 rows x 48k bf16 hi/lo
__device__ __forceinline__ void stageA_cp(const ushortt* __restrict__ AH,
                                          const ushortt* __restrict__ AL,
                                          int lda, int k0, unsigned sbuf, int tid)
{
    for (int idx = tid; idx < 768; idx += NTH) {
        const int r = idx / 6, cc = idx % 6;
        const unsigned d = sbuf + r * 112 + cc * 16;
        const int go = r * lda + k0 + cc * 8;
        cpa16(d,          AH + go);
        cpa16(d + OFF_AL, AL + go);
    }
}
// mode-a B staging via cp.async: 64 rows x 48k bf16 hi/lo
__device__ __forceinline__ void stageB_cp(const ushortt* __restrict__ BH,
                                          const ushortt* __restrict__ BL,
                                          int ldb, int k0, unsigned sbuf, int tid)
{
    for (int idx = tid; idx < 384; idx += NTH) {
        const int r = idx / 6, cc = idx % 6;
        const unsigned d = sbuf + OFF_BH + r * 112 + cc * 16;
        const int go = r * ldb + k0 + cc * 8;
        cpa16(d,                     BH + go);
        cpa16(d + (OFF_BL - OFF_BH), BL + go);
    }
}
// mode-b B load: 48 rows x 64 n fp32 -> 3 float4/thread
__device__ __forceinline__ void ldgB_w(const float* __restrict__ W, int ldw,
                                       int n0, int k0, float4* br, int tid)
{
#pragma unroll
    for (int t = 0; t < 3; ++t) {
        const int idx = tid + t * NTH;
        const int r = idx >> 4, c4 = (idx & 15) * 4;
        br[t] = *(const float4*)&W[(size_t)(k0 + r) * ldw + n0 + c4];
    }
}
// mode-b B convert+store into [k][n] bf16 hi/lo tile (pitch 144B)
__device__ __forceinline__ void stsB_w(const float4* br, char* gsbuf, int tid)
{
#pragma unroll
    for (int t = 0; t < 3; ++t) {
        const int idx = tid + t * NTH;
        const int r = idx >> 4, c4 = (idx & 15) * 4;
        unsigned h0, l0, h1, l1;
        split2(br[t].x, br[t].y, h0, l0);
        split2(br[t].z, br[t].w, h1, l1);
        char* p = gsbuf + OFF_BH + r * BPITCH + c4 * 2;
        *(uint2*)p = make_uint2(h0, h1);
        *(uint2*)(p + (OFF_BL - OFF_BH)) = make_uint2(l0, l1);
    }
}

// A fragments (direct LDS, proven in R9)
__device__ __forceinline__ void load_afrag(const char* buf, int wm, int g, int tg,
                                           int kk, unsigned ah[2][4], unsigned al[2][4])
{
    const unsigned* AH = (const unsigned*)buf;
    const unsigned* AL = (const unsigned*)(buf + OFF_AL);
    const int kc = kk * 8 + tg;
#pragma unroll
    for (int i = 0; i < 2; ++i) {
        const int r0 = (wm * 32 + i * 16 + g) * PITCHU;
        const int r1 = r0 + 8 * PITCHU;
        ah[i][0] = AH[r0 + kc];     ah[i][1] = AH[r1 + kc];
        ah[i][2] = AH[r0 + kc + 4]; ah[i][3] = AH[r1 + kc + 4];
        al[i][0] = AL[r0 + kc];     al[i][1] = AL[r1 + kc];
        al[i][2] = AL[r0 + kc + 4]; al[i][3] = AL[r1 + kc + 4];
    }
}

// mode-a chunk (B [n][k] direct LDS) — R9-proven
__device__ __forceinline__ void mma_chunk_a(const char* buf, int wm, int wn,
                                            int g, int tg, float acc[2][4][4])
{
    const unsigned* BH = (const unsigned*)(buf + OFF_BH);
    const unsigned* BL = (const unsigned*)(buf + OFF_BL);
#pragma unroll
    for (int kk = 0; kk < 3; ++kk) {
        unsigned ah[2][4], al[2][4];
        load_afrag(buf, wm, g, tg, kk, ah, al);
        const int kc = kk * 8 + tg;
#pragma unroll
        for (int j = 0; j < 4; ++j) {
            const int nrow = (wn * 32 + j * 8 + g) * PITCHU;
            const unsigned bh0 = BH[nrow + kc], bh1 = BH[nrow + kc + 4];
            const unsigned bl0 = BL[nrow + kc], bl1 = BL[nrow + kc + 4];
#pragma unroll
            for (int i = 0; i < 2; ++i) {
                mma16816(acc[i][j], ah[i][0], ah[i][1], ah[i][2], ah[i][3], bh0, bh1);
                mma16816(acc[i][j], ah[i][0], ah[i][1], ah[i][2], ah[i][3], bl0, bl1);
                mma16816(acc[i][j], al[i][0], al[i][1], al[i][2], al[i][3], bh0, bh1);
            }
        }
    }
}

// mode-b chunk (B [k][n] via ldmatrix.x4.trans)
__device__ __forceinline__ void mma_chunk_w(const char* buf, unsigned bufu,
                                            int wm, int wn, int g, int tg,
                                            int krow_off, int joff_b,
                                            float acc[2][4][4])
{
#pragma unroll
    for (int kk = 0; kk < 3; ++kk) {
        unsigned ah[2][4], al[2][4];
        load_afrag(buf, wm, g, tg, kk, ah, al);
        const unsigned rowa = bufu + OFF_BH + (unsigned)((kk * 16 + krow_off) * BPITCH) + joff_b;
#pragma unroll
        for (int j2 = 0; j2 < 2; ++j2) {
            const unsigned ba = rowa + j2 * 32;
            unsigned bh0, bh1, bh2, bh3, bl0, bl1, bl2, bl3;
            ldmx4t(bh0, bh1, bh2, bh3, ba);
            ldmx4t(bl0, bl1, bl2, bl3, ba + (OFF_BL - OFF_BH));
            const int j0 = j2 * 2, j1 = j0 + 1;
#pragma unroll
            for (int i = 0; i < 2; ++i) {
                mma16816(acc[i][j0], ah[i][0], ah[i][1], ah[i][2], ah[i][3], bh0, bh1);
                mma16816(acc[i][j0], ah[i][0], ah[i][1], ah[i][2], ah[i][3], bl0, bl1);
                mma16816(acc[i][j0], al[i][0], al[i][1], al[i][2], al[i][3], bh0, bh1);
                mma16816(acc[i][j1], ah[i][0], ah[i][1], ah[i][2], ah[i][3], bh2, bh3);
                mma16816(acc[i][j1], ah[i][0], ah[i][1], ah[i][2], ah[i][3], bl2, bl3);
                mma16816(acc[i][j1], al[i][0], al[i][1], al[i][2], al[i][3], bh2, bh3);
            }
        }
    }
}

// mode-a tile (activations both sides) — R9-proven pipeline
__device__ __forceinline__ void run_tile_a(
    const ushortt* AH, const ushortt* AL, int lda,
    const ushortt* BH, const ushortt* BL, int ldb,
    int K, char* gs, unsigned gs_u32, int tid, float acc[2][4][4])
{
    const int wm = (tid >> 5) & 3, wn = tid >> 7;
    const int g = (tid & 31) >> 2, tg = tid & 3;
    const int nc = K / CHUNK;
    stageA_cp(AH, AL, lda, 0, gs_u32, tid);
    stageB_cp(BH, BL, ldb, 0, gs_u32, tid);
    CPA_COMMIT();
    for (int c = 0; c < nc; ++c) {
        CPA_WAIT0();
        __syncthreads();
        if (c + 1 < nc) {
            const unsigned nb = gs_u32 + ((c + 1) & 1) * BUF_BYTES;
            stageA_cp(AH, AL, lda, (c + 1) * CHUNK, nb, tid);
            stageB_cp(BH, BL, ldb, (c + 1) * CHUNK, nb, tid);
            CPA_COMMIT();
        }
        mma_chunk_a(gs + (c & 1) * BUF_BYTES, wm, wn, g, tg, acc);
        __syncthreads();
    }
}

// mode-b tile (A activations bf16, B weights fp32 [k][n])
__device__ __forceinline__ void run_tile_w(
    const ushortt* AH, const ushortt* AL, int lda,
    const float* W, int ldw, int n0,
    int K, char* gs, unsigned gs_u32, int tid, float acc[2][4][4])
{
    const int lane = tid & 31;
    const int wm = (tid >> 5) & 3, wn = tid >> 7;
    const int g = lane >> 2, tg = lane & 3;
    const int krow_off = ((lane >> 3) & 1) * 8 + (lane & 7);
    const int joff_b = (wn * 32 + ((lane >> 4) & 1) * 8) * 2;

    float4 br[3];
    const int nc = K / CHUNK;
    stageA_cp(AH, AL, lda, 0, gs_u32, tid);
    CPA_COMMIT();
    ldgB_w(W, ldw, n0, 0, br, tid);
    stsB_w(br, gs, tid);
    for (int c = 0; c < nc; ++c) {
        CPA_WAIT0();
        __syncthreads();
        if (c + 1 < nc) {
            stageA_cp(AH, AL, lda, (c + 1) * CHUNK,
                      gs_u32 + ((c + 1) & 1) * BUF_BYTES, tid);
            CPA_COMMIT();
            ldgB_w(W, ldw, n0, (c + 1) * CHUNK, br, tid);
        }
        mma_chunk_w(gs + (c & 1) * BUF_BYTES, gs_u32 + (c & 1) * BUF_BYTES,
                    wm, wn, g, tg, krow_off, joff_b, acc);
        if (c + 1 < nc) stsB_w(br, gs + ((c + 1) & 1) * BUF_BYTES, tid);
        __syncthreads();
    }
}

// ---------------------------------------------------------------------------
__global__ __launch_bounds__(NTH)
void fused_kernel(const float* __restrict__ hid,   const float* __restrict__ act,
                  const int*   __restrict__ state,
                  const float* __restrict__ W_enc, const float* __restrict__ b_enc,
                  const float* __restrict__ Wq,  const float* __restrict__ bq,
                  const float* __restrict__ Wk,  const float* __restrict__ bk,
                  const float* __restrict__ Wv,  const float* __restrict__ bv,
                  const float* __restrict__ Wiq, const float* __restrict__ biq,
                  const float* __restrict__ Wik, const float* __restrict__ bik,
                  const float* __restrict__ Wiv, const float* __restrict__ biv,
                  const float* __restrict__ Wo,  const float* __restrict__ bo,
                  const float* __restrict__ W_O,
                  const float* __restrict__ W_val, const float* __restrict__ b_val,
                  const float* __restrict__ W_adv, const float* __restrict__ b_adv,
                  float* __restrict__ out)
{
    extern __shared__ char gs[];
    __shared__ unsigned s_sense;
    __shared__ int s_sn;

    const int tid = threadIdx.x;
    const int bx  = blockIdx.x;
    const int wid = tid >> 5, lane = tid & 31;
    const int wm = wid & 3, wn = wid >> 2;
    const int g = lane >> 2, tg = lane & 3;
    const unsigned gs_u32 = su32(gs);
    if (tid == 0) s_sense = g_bar_sense;   // self-consistent across replays
    __syncthreads();

    // =====================================================================
    // PHASE 0: 0..15 obs encode + action -> g_Cb ; 16..24 head combine ; 25 mask
    // =====================================================================
    if (bx < 16) {
        const int base = bx * 16;
        {
            const int ai = base + (tid >> 4);
            const int c  = tid & 15;
            float o = b_enc[c];
            for (int d = 0; d < HID; ++d)
                o += hid[ai * HID + d] * W_enc[d * 16 + c];
            ushortt h, l; split1(o, h, l);
            g_Cb[0][ai * DD + c] = h;
            g_Cb[1][ai * DD + c] = l;
        }
        for (int idx = tid; idx < 16 * 128; idx += NTH) {
            const int ai = base + (idx >> 7), col = idx & 127;
            ushortt h, l; split1(act[ai * HID + col], h, l);
            g_Cb[0][ai * DD + 16 + col] = h;
            g_Cb[1][ai * DD + 16 + col] = l;
        }
    } else if (bx < 25) {
        const int part = bx - 16;
        float* W2 = (float*)gs;   // 576*6 floats
        for (int r = tid; r < EE; r += NTH) {
            float a[6] = {};
            for (int k = 0; k < DD; ++k) {
                const float w = W_O[r * DD + k];
                a[0] += w * W_val[k];
#pragma unroll
                for (int j = 0; j < ACT; ++j) a[1 + j] += w * W_adv[k * ACT + j];
            }
#pragma unroll
            for (int j = 0; j < 6; ++j) W2[r * 6 + j] = a[j];
        }
        __syncthreads();
        {
            const int e  = part * 64 + (tid >> 2);
            const int f0 = (tid & 3) * 144;
            float a[6] = {};
            for (int f = f0; f < f0 + 144; ++f) {
                const float w = Wo[e * EE + f];
#pragma unroll
                for (int j = 0; j < 6; ++j) a[j] += w * W2[f * 6 + j];
            }
#pragma unroll
            for (int j = 0; j < 6; ++j) {
                a[j] += __shfl_xor_sync(0xffffffffu, a[j], 1);
                a[j] += __shfl_xor_sync(0xffffffffu, a[j], 2);
            }
            if ((tid & 3) == 0) {
#pragma unroll
                for (int j = 0; j < 6; ++j) g_Wfin[e * 6 + j] = a[j];
            }
        }
        if (part == 0 && tid < 6) {
            float s = 0.f;
            for (int f = 0; f < EE; ++f) s += bo[f] * W2[f * 6 + tid];
            g_bfin[tid] = s;
        }
    } else if (bx == 25) {
        int* px = (int*)gs; int* py = px + NA;
        px[tid] = state[2 * tid]; py[tid] = state[2 * tid + 1];
        __syncthreads();
        unsigned wb[8] = {0, 0, 0, 0, 0, 0, 0, 0};
        const int xi = px[tid], yi = py[tid];
        for (int j = tid + 1; j < NA; ++j) {
            const int dx = abs(xi - px[j]);
            const int dy = abs(yi - py[j]);
            if (dx <= OBS_RX && dy <= OBS_RY) wb[j >> 5] |= (1u << (j & 31));
        }
#pragma unroll
        for (int q = 0; q < 8; ++q) g_mask[tid * 8 + q] = wb[q];
    }
    GRID_BAR();

    // =====================================================================
    // PHASE B1: P(z) = C @ Wz + bz   (54 jobs: 3z x 2m x 9n, K=144)
    // =====================================================================
    if (bx < 54) {
        const int z  = bx / 18, r = bx % 18;
        const int m0 = (r / 9) * 128, n0 = (r % 9) * 64;
        const float* Wz = (z == 0) ? Wq : (z == 1) ? Wk : Wv;
        const float* bz = (z == 0) ? bq : (z == 1) ? bk : bv;
        float acc[2][4][4] = {};
        run_tile_w(&g_Cb[0][0] + m0 * DD, &g_Cb[1][0] + m0 * DD, DD,
                   Wz, EE, n0, DD, gs, gs_u32, tid, acc);
#pragma unroll
        for (int i = 0; i < 2; ++i) {
            const int row = m0 + wm * 32 + i * 16 + g;
#pragma unroll
            for (int j = 0; j < 4; ++j) {
                const int col = n0 + wn * 32 + j * 8 + 2 * tg;
                const float b0 = bz[col], b1 = bz[col + 1];
                unsigned h, l;
                split2(acc[i][j][0] + b0, acc[i][j][1] + b1, h, l);
                *(unsigned*)&g_Pb[0][z][row * EE + col] = h;
                *(unsigned*)&g_Pb[1][z][row * EE + col] = l;
                split2(acc[i][j][2] + b0, acc[i][j][3] + b1, h, l);
                *(unsigned*)&g_Pb[0][z][(row + 8) * EE + col] = h;
                *(unsigned*)&g_Pb[1][z][(row + 8) * EE + col] = l;
            }
        }
    }
    GRID_BAR();

    // =====================================================================
    // PHASE B2: qkv(z) = P(z) @ Wiz + biz   (54 jobs, K=576)
    // =====================================================================
    if (bx < 54) {
        const int z  = bx / 18, r = bx % 18;
        const int m0 = (r / 9) * 128, n0 = (r % 9) * 64;
        const float* Wiz = (z == 0) ? Wiq : (z == 1) ? Wik : Wiv;
        const float* biz = (z == 0) ? biq : (z == 1) ? bik : biv;
        float acc[2][4][4] = {};
        run_tile_w(&g_Pb[0][z][0] + m0 * EE, &g_Pb[1][z][0] + m0 * EE, EE,
                   Wiz, EE, n0, EE, gs, gs_u32, tid, acc);
#pragma unroll
        for (int i = 0; i < 2; ++i) {
            const int row = m0 + wm * 32 + i * 16 + g;
#pragma unroll
            for (int j = 0; j < 4; ++j) {
                const int col = n0 + wn * 32 + j * 8 + 2 * tg;
                const float b0 = biz[col], b1 = biz[col + 1];
                const float v0 = acc[i][j][0] + b0, v1 = acc[i][j][1] + b1;
                const float v2 = acc[i][j][2] + b0, v3 = acc[i][j][3] + b1;
                if (z < 2) {
                    unsigned h, l;
                    split2(v0, v1, h, l);
                    *(unsigned*)&g_Qb[0][z][row * EE + col] = h;
                    *(unsigned*)&g_Qb[1][z][row * EE + col] = l;
                    split2(v2, v3, h, l);
                    *(unsigned*)&g_Qb[0][z][(row + 8) * EE + col] = h;
                    *(unsigned*)&g_Qb[1][z][(row + 8) * EE + col] = l;
                } else {
                    *(float2*)&g_Qv[row * EE + col]       = make_float2(v0, v1);
                    *(float2*)&g_Qv[(row + 8) * EE + col] = make_float2(v2, v3);
                }
            }
        }
    }
    GRID_BAR();

    // =====================================================================
    // PHASE S: S[h] = (1/12) q2_h @ k2_h^T  (32 jobs: 4h x 2m x 4n, K=144)
    // =====================================================================
    if (bx < 32) {
        const int h  = bx / 8, r = bx % 8;
        const int m0 = (r / 4) * 128, n0 = (r % 4) * 64;
        float acc[2][4][4] = {};
        run_tile_a(&g_Qb[0][0][0] + m0 * EE + h * HDH, &g_Qb[1][0][0] + m0 * EE + h * HDH, EE,
                   &g_Qb[0][1][0] + n0 * EE + h * HDH, &g_Qb[1][1][0] + n0 * EE + h * HDH, EE,
                   HDH, gs, gs_u32, tid, acc);
        float* Cd = g_S + h * NA * NA;
#pragma unroll
        for (int i = 0; i < 2; ++i) {
            const int row = m0 + wm * 32 + i * 16 + g;
#pragma unroll
            for (int j = 0; j < 4; ++j) {
                const int col = n0 + wn * 32 + j * 8 + 2 * tg;
                *(float2*)&Cd[row * NA + col] =
                    make_float2(acc[i][j][0] * (1.f / 12.f), acc[i][j][1] * (1.f / 12.f));
                *(float2*)&Cd[(row + 8) * NA + col] =
                    make_float2(acc[i][j][2] * (1.f / 12.f), acc[i][j][3] * (1.f / 12.f));
            }
        }
    }
    GRID_BAR();

    // =====================================================================
    // PHASE DE: per-agent masked softmax-sum + context + final head
    // =====================================================================
    {
        float* w   = (float*)gs;             // NH*NA floats  (4096B)
        int*   Jl  = (int*)(gs + 4096);      // NA ints       (1024B)
        float* red = (float*)(gs + 5120);    // 6 floats
        for (int i = bx; i < NA; i += NB) {
            for (int q = tid; q < NH * NA; q += NTH) w[q] = 0.f;
            if (tid < 6) red[tid] = 0.f;
            if (tid == 0) {
                int n = 0;
                for (int q = 0; q < 8; ++q) {
                    unsigned bits = g_mask[i * 8 + q];
                    while (bits) {
                        const int b = __ffs(bits) - 1;
                        Jl[n++] = q * 32 + b;
                        bits &= bits - 1;
                    }
                }
                s_sn = n;
            }
            __syncthreads();
            const int n = s_sn;
            float a6[6] = {};
            if (n > 0) {
                for (int p = tid; p < NH * n; p += NTH) {
                    const int h  = p & 3;
                    const int jj = Jl[p >> 2];
                    const float* row = g_S + h * NA * NA + jj * NA;
                    float m = -1e30f;
                    for (int q = 0; q < n; ++q) m = fmaxf(m, row[Jl[q]]);
                    float sum = 0.f;
                    for (int q = 0; q < n; ++q) sum += expf(row[Jl[q]] - m);
                    const float inv = 1.f / sum;
                    for (int q = 0; q < n; ++q)
                        atomicAdd(&w[h * NA + q], expf(row[Jl[q]] - m) * inv);
                }
                __syncthreads();
                for (int e = tid; e < EE; e += NTH) {
                    const int h = e / HDH;
                    float G = 0.f;
                    for (int q = 0; q < n; ++q)
                        G += w[h * NA + q] * g_Qv[Jl[q] * EE + e];
                    const float* Wr = g_Wfin + e * 6;
#pragma unroll
                    for (int j = 0; j < 6; ++j) a6[j] += G * Wr[j];
                }
            }
#pragma unroll
            for (int j = 0; j < 6; ++j)
#pragma unroll
                for (int o = 16; o > 0; o >>= 1)
                    a6[j] += __shfl_xor_sync(0xffffffffu, a6[j], o);
            if (lane == 0) {
#pragma unroll
                for (int j = 0; j < 6; ++j) atomicAdd(&red[j], a6[j]);
            }
            __syncthreads();
            if (tid == 0) {
                const float c = (float)n;
                const float V = red[0] + c * g_bfin[0] + b_val[0];
                float A[ACT], mean = 0.f;
#pragma unroll
                for (int j = 0; j < ACT; ++j) {
                    A[j] = red[1 + j] + c * g_bfin[1 + j] + b_adv[j];
                    mean += A[j];
                }
                mean *= (1.f / ACT);
#pragma unroll
                for (int j = 0; j < ACT; ++j) out[i * ACT + j] = V + A[j] - mean;
            }
            __syncthreads();
        }
    }
}

// ---------------------------------------------------------------------------
extern "C" void kernel_launch(void* const* d_in, const int* in_sizes, int n_in,
                              void* d_out, int out_size)
{
    const float *hid, *act, *W_enc, *b_enc, *Wq, *bq, *Wk, *bk, *Wv, *bv;
    const float *Wiq, *biq, *Wik, *bik, *Wiv, *biv, *Wo, *bo, *W_O;
    const float *W_val, *b_val, *W_adv, *b_adv;
    const int* state;

    if (n_in >= 3 && in_sizes[2] == 512) {
        hid   = (const float*)d_in[0];  act  = (const float*)d_in[1];
        state = (const int*)  d_in[2];
        W_enc = (const float*)d_in[3];  b_enc = (const float*)d_in[4];
        Wq  = (const float*)d_in[5];    bq  = (const float*)d_in[6];
        Wk  = (const float*)d_in[7];    bk  = (const float*)d_in[8];
        Wv  = (const float*)d_in[9];    bv  = (const float*)d_in[10];
        Wiq = (const float*)d_in[11];   biq = (const float*)d_in[12];
        Wik = (const float*)d_in[13];   bik = (const float*)d_in[14];
        Wiv = (const float*)d_in[15];   biv = (const float*)d_in[16];
        Wo  = (const float*)d_in[17];   bo  = (const float*)d_in[18];
        W_O = (const float*)d_in[19];
        W_val = (const float*)d_in[20]; b_val = (const float*)d_in[21];
        W_adv = (const float*)d_in[22]; b_adv = (const float*)d_in[23];
    } else {
        hid   = (const float*)d_in[0];  act  = (const float*)d_in[1];
        W_enc = (const float*)d_in[2];  b_enc = (const float*)d_in[3];
        Wq  = (const float*)d_in[4];    bq  = (const float*)d_in[5];
        Wk  = (const float*)d_in[6];    bk  = (const float*)d_in[7];
        Wv  = (const float*)d_in[8];    bv  = (const float*)d_in[9];
        Wiq = (const float*)d_in[10];   biq = (const float*)d_in[11];
        Wik = (const float*)d_in[12];   bik = (const float*)d_in[13];
        Wiv = (const float*)d_in[14];   biv = (const float*)d_in[15];
        Wo  = (const float*)d_in[16];   bo  = (const float*)d_in[17];
        W_O = (const float*)d_in[18];
        W_val = (const float*)d_in[19]; b_val = (const float*)d_in[20];
        W_adv = (const float*)d_in[21]; b_adv = (const float*)d_in[22];
        state = (const int*)  d_in[23];
    }

    static bool attr_set = false;
    if (!attr_set) {
        cudaFuncSetAttribute(fused_kernel,
                             cudaFuncAttributeMaxDynamicSharedMemorySize, SMEM_DYN);
        attr_set = true;
    }

    fused_kernel<<<NB, NTH, SMEM_DYN>>>(hid, act, state, W_enc, b_enc,
                                        Wq, bq, Wk, bk, Wv, bv,
                                        Wiq, biq, Wik, bik, Wiv, biv,
                                        Wo, bo, W_O, W_val, b_val, W_adv, b_adv,
                                        (float*)d_out);
}

// round 11
// speedup vs baseline: 1.3448x; 1.0044x over previous
#include <cuda_runtime.h>
#include <cuda_bf16.h>
#include <math.h>
#include <stdint.h>

typedef unsigned short ushortt;

// ---------------------------------------------------------------------------
#define NA   256
#define HID  128
#define ACT  5
#define NH   4
#define DD   144
#define EE   576
#define HDH  144
#define OBS_RX 4
#define OBS_RY 2
#define NB   148
#define NTH  512          // 16 warps/CTA (4 per SMSP)

#define PITCHU 28          // A / mode-a B row pitch in u32 (112B)
#define BPITCH 144         // mode-b B row pitch bytes
#define CHUNK  48
#define OFF_AL 14336
#define OFF_BH 28672
#define OFF_BL 35840
#define BUF_BYTES 43008
#define SMEM_DYN  (2 * BUF_BYTES)   // 86016

// ---------------------------------------------------------------------------
__device__ __align__(16) ushortt g_Cb[2][NA * DD];
__device__ __align__(16) ushortt g_Pb[2][3][NA * EE];
__device__ __align__(16) ushortt g_Qb[2][2][NA * EE];
__device__ __align__(16) float   g_Qv[NA * EE];
__device__ __align__(16) float   g_S[NH * NA * NA];
__device__ unsigned g_mask[NA * 8];
__device__ __align__(16) float   g_Wfin[EE * 6];
__device__ float    g_bfin[6];
__device__ unsigned          g_bar_count;
__device__ volatile unsigned g_bar_sense;

// ---------------------------------------------------------------------------
__device__ __forceinline__ unsigned su32(const void* p) {
    unsigned a;
    asm("{ .reg .u64 t; cvta.to.shared.u64 t, %1; cvt.u32.u64 %0, t; }"
        : "=r"(a) : "l"(p));
    return a;
}
__device__ __forceinline__ void cpa16(unsigned s, const void* g) {
    asm volatile("cp.async.cg.shared.global [%0], [%1], 16;" :: "r"(s), "l"(g));
}
#define CPA_COMMIT() asm volatile("cp.async.commit_group;" ::: "memory")
#define CPA_WAIT0()  asm volatile("cp.async.wait_group 0;" ::: "memory")

__device__ __forceinline__ void mma16816(float c[4],
    unsigned a0, unsigned a1, unsigned a2, unsigned a3,
    unsigned b0, unsigned b1)
{
    asm volatile(
        "mma.sync.aligned.m16n8k16.row.col.f32.bf16.bf16.f32 "
        "{%0,%1,%2,%3}, {%4,%5,%6,%7}, {%8,%9}, {%0,%1,%2,%3};"
        : "+f"(c[0]), "+f"(c[1]), "+f"(c[2]), "+f"(c[3])
        : "r"(a0), "r"(a1), "r"(a2), "r"(a3), "r"(b0), "r"(b1));
}
__device__ __forceinline__ void ldmx4t(unsigned& r0, unsigned& r1,
                                       unsigned& r2, unsigned& r3, unsigned a)
{
    asm volatile("ldmatrix.sync.aligned.m8n8.x4.trans.shared.b16 {%0,%1,%2,%3}, [%4];"
                 : "=r"(r0), "=r"(r1), "=r"(r2), "=r"(r3) : "r"(a));
}

__device__ __forceinline__ void split1(float v, ushortt& h, ushortt& l) {
    __nv_bfloat16 hb = __float2bfloat16(v);
    float r = v - __bfloat162float(hb);
    __nv_bfloat16 lb = __float2bfloat16(r);
    h = __bfloat16_as_ushort(hb);
    l = __bfloat16_as_ushort(lb);
}
__device__ __forceinline__ void split2(float v0, float v1, unsigned& h, unsigned& l) {
    ushortt h0, l0, h1, l1;
    split1(v0, h0, l0); split1(v1, h1, l1);
    h = ((unsigned)h1 << 16) | h0;
    l = ((unsigned)l1 << 16) | l0;
}

#define GRID_BAR()                                                        \
    do {                                                                  \
        __threadfence();                                                  \
        __syncthreads();                                                  \
        if (tid == 0) {                                                   \
            unsigned target = s_sense ^ 1u;                               \
            s_sense = target;                                             \
            unsigned aidx = atomicAdd(&g_bar_count, 1u);                  \
            if (aidx == (unsigned)(NB - 1)) {                             \
                g_bar_count = 0u;                                         \
                __threadfence();                                          \
                g_bar_sense = target;                                     \
            } else {                                                      \
                while (g_bar_sense != target) __nanosleep(64);            \
            }                                                             \
        }                                                                 \
        __syncthreads();                                                  \
        __threadfence();                                                  \
    } while (0)

// ---------------------------------------------------------------------------
__device__ __forceinline__ void stageA_cp(const ushortt* __restrict__ AH,
                                          const ushortt* __restrict__ AL,
                                          int lda, int k0, unsigned sbuf, int tid)
{
    for (int idx = tid; idx < 768; idx += NTH) {
        const int r = idx / 6, cc = idx % 6;
        const unsigned d = sbuf + r * 112 + cc * 16;
        const int go = r * lda + k0 + cc * 8;
        cpa16(d,          AH + go);
        cpa16(d + OFF_AL, AL + go);
    }
}
__device__ __forceinline__ void stageB_cp(const ushortt* __restrict__ BH,
                                          const ushortt* __restrict__ BL,
                                          int ldb, int k0, unsigned sbuf, int tid)
{
    for (int idx = tid; idx < 384; idx += NTH) {
        const int r = idx / 6, cc = idx % 6;
        const unsigned d = sbuf + OFF_BH + r * 112 + cc * 16;
        const int go = r * ldb + k0 + cc * 8;
        cpa16(d,                     BH + go);
        cpa16(d + (OFF_BL - OFF_BH), BL + go);
    }
}
// mode-b weight load: 48 rows x 64 n fp32 -> <=2 float4/thread
__device__ __forceinline__ void ldgB_w(const float* __restrict__ W, int ldw,
                                       int n0, int k0, float4 br[2], int tid)
{
#pragma unroll
    for (int t = 0; t < 2; ++t) {
        const int idx = tid + t * NTH;
        if (idx < 768) {
            const int r = idx >> 4, c4 = (idx & 15) * 4;
            br[t] = *(const float4*)&W[(size_t)(k0 + r) * ldw + n0 + c4];
        }
    }
}
__device__ __forceinline__ void stsB_w(const float4 br[2], char* gsbuf, int tid)
{
#pragma unroll
    for (int t = 0; t < 2; ++t) {
        const int idx = tid + t * NTH;
        if (idx < 768) {
            const int r = idx >> 4, c4 = (idx & 15) * 4;
            unsigned h0, l0, h1, l1;
            split2(br[t].x, br[t].y, h0, l0);
            split2(br[t].z, br[t].w, h1, l1);
            char* p = gsbuf + OFF_BH + r * BPITCH + c4 * 2;
            *(uint2*)p = make_uint2(h0, h1);
            *(uint2*)(p + (OFF_BL - OFF_BH)) = make_uint2(l0, l1);
        }
    }
}

// A fragments (direct LDS) — layout proven in R9/R10
__device__ __forceinline__ void load_afrag(const char* buf, int wm, int g, int tg,
                                           int kk, unsigned ah[2][4], unsigned al[2][4])
{
    const unsigned* AH = (const unsigned*)buf;
    const unsigned* AL = (const unsigned*)(buf + OFF_AL);
    const int kc = kk * 8 + tg;
#pragma unroll
    for (int i = 0; i < 2; ++i) {
        const int r0 = (wm * 32 + i * 16 + g) * PITCHU;
        const int r1 = r0 + 8 * PITCHU;
        ah[i][0] = AH[r0 + kc];     ah[i][1] = AH[r1 + kc];
        ah[i][2] = AH[r0 + kc + 4]; ah[i][3] = AH[r1 + kc + 4];
        al[i][0] = AL[r0 + kc];     al[i][1] = AL[r1 + kc];
        al[i][2] = AL[r0 + kc + 4]; al[i][3] = AL[r1 + kc + 4];
    }
}

// mode-a chunk: warp covers 32m x 16n (2 j-frags), B [n][k] direct LDS
__device__ __forceinline__ void mma_chunk_a(const char* buf, int wm, int wn,
                                            int g, int tg, float acc[2][2][4])
{
    const unsigned* BH = (const unsigned*)(buf + OFF_BH);
    const unsigned* BL = (const unsigned*)(buf + OFF_BL);
#pragma unroll
    for (int kk = 0; kk < 3; ++kk) {
        unsigned ah[2][4], al[2][4];
        load_afrag(buf, wm, g, tg, kk, ah, al);
        const int kc = kk * 8 + tg;
#pragma unroll
        for (int j = 0; j < 2; ++j) {
            const int nrow = (wn * 16 + j * 8 + g) * PITCHU;
            const unsigned bh0 = BH[nrow + kc], bh1 = BH[nrow + kc + 4];
            const unsigned bl0 = BL[nrow + kc], bl1 = BL[nrow + kc + 4];
#pragma unroll
            for (int i = 0; i < 2; ++i) {
                mma16816(acc[i][j], ah[i][0], ah[i][1], ah[i][2], ah[i][3], bh0, bh1);
                mma16816(acc[i][j], ah[i][0], ah[i][1], ah[i][2], ah[i][3], bl0, bl1);
                mma16816(acc[i][j], al[i][0], al[i][1], al[i][2], al[i][3], bh0, bh1);
            }
        }
    }
}

// mode-b chunk: B [k][n] via one ldmatrix.x4.trans per kk (covers 16 cols)
__device__ __forceinline__ void mma_chunk_w(const char* buf, unsigned bufu,
                                            int wm, int g, int tg,
                                            int krow_off, int joff_b,
                                            float acc[2][2][4])
{
#pragma unroll
    for (int kk = 0; kk < 3; ++kk) {
        unsigned ah[2][4], al[2][4];
        load_afrag(buf, wm, g, tg, kk, ah, al);
        const unsigned ba = bufu + OFF_BH +
            (unsigned)((kk * 16 + krow_off) * BPITCH) + joff_b;
        unsigned bh0, bh1, bh2, bh3, bl0, bl1, bl2, bl3;
        ldmx4t(bh0, bh1, bh2, bh3, ba);
        ldmx4t(bl0, bl1, bl2, bl3, ba + (OFF_BL - OFF_BH));
#pragma unroll
        for (int i = 0; i < 2; ++i) {
            mma16816(acc[i][0], ah[i][0], ah[i][1], ah[i][2], ah[i][3], bh0, bh1);
            mma16816(acc[i][0], ah[i][0], ah[i][1], ah[i][2], ah[i][3], bl0, bl1);
            mma16816(acc[i][0], al[i][0], al[i][1], al[i][2], al[i][3], bh0, bh1);
            mma16816(acc[i][1], ah[i][0], ah[i][1], ah[i][2], ah[i][3], bh2, bh3);
            mma16816(acc[i][1], ah[i][0], ah[i][1], ah[i][2], ah[i][3], bl2, bl3);
            mma16816(acc[i][1], al[i][0], al[i][1], al[i][2], al[i][3], bh2, bh3);
        }
    }
}

// mode-a tile (activations both sides)
__device__ __forceinline__ void run_tile_a(
    const ushortt* AH, const ushortt* AL, int lda,
    const ushortt* BH, const ushortt* BL, int ldb,
    int K, char* gs, unsigned gs_u32, int tid, float acc[2][2][4])
{
    const int wm = (tid >> 5) & 3, wn = tid >> 7;
    const int g = (tid & 31) >> 2, tg = tid & 3;
    const int nc = K / CHUNK;
    stageA_cp(AH, AL, lda, 0, gs_u32, tid);
    stageB_cp(BH, BL, ldb, 0, gs_u32, tid);
    CPA_COMMIT();
    for (int c = 0; c < nc; ++c) {
        CPA_WAIT0();
        __syncthreads();
        if (c + 1 < nc) {
            const unsigned nb = gs_u32 + ((c + 1) & 1) * BUF_BYTES;
            stageA_cp(AH, AL, lda, (c + 1) * CHUNK, nb, tid);
            stageB_cp(BH, BL, ldb, (c + 1) * CHUNK, nb, tid);
            CPA_COMMIT();
        }
        mma_chunk_a(gs + (c & 1) * BUF_BYTES, wm, wn, g, tg, acc);
        __syncthreads();
    }
}

// mode-b tile (A activations bf16, B weights fp32 [k][n])
__device__ __forceinline__ void run_tile_w(
    const ushortt* AH, const ushortt* AL, int lda,
    const float* W, int ldw, int n0,
    int K, char* gs, unsigned gs_u32, int tid, float acc[2][2][4])
{
    const int lane = tid & 31;
    const int wm = (tid >> 5) & 3, wn = tid >> 7;
    const int g = lane >> 2, tg = lane & 3;
    const int krow_off = ((lane >> 3) & 1) * 8 + (lane & 7);
    const int joff_b = (wn * 16 + ((lane >> 4) & 1) * 8) * 2;

    float4 br[2];
    const int nc = K / CHUNK;
    stageA_cp(AH, AL, lda, 0, gs_u32, tid);
    CPA_COMMIT();
    ldgB_w(W, ldw, n0, 0, br, tid);
    stsB_w(br, gs, tid);
    for (int c = 0; c < nc; ++c) {
        CPA_WAIT0();
        __syncthreads();
        if (c + 1 < nc) {
            stageA_cp(AH, AL, lda, (c + 1) * CHUNK,
                      gs_u32 + ((c + 1) & 1) * BUF_BYTES, tid);
            CPA_COMMIT();
            ldgB_w(W, ldw, n0, (c + 1) * CHUNK, br, tid);
        }
        mma_chunk_w(gs + (c & 1) * BUF_BYTES, gs_u32 + (c & 1) * BUF_BYTES,
                    wm, g, tg, krow_off, joff_b, acc);
        if (c + 1 < nc) stsB_w(br, gs + ((c + 1) & 1) * BUF_BYTES, tid);
        __syncthreads();
    }
}

// ---------------------------------------------------------------------------
__global__ __launch_bounds__(NTH)
void fused_kernel(const float* __restrict__ hid,   const float* __restrict__ act,
                  const int*   __restrict__ state,
                  const float* __restrict__ W_enc, const float* __restrict__ b_enc,
                  const float* __restrict__ Wq,  const float* __restrict__ bq,
                  const float* __restrict__ Wk,  const float* __restrict__ bk,
                  const float* __restrict__ Wv,  const float* __restrict__ bv,
                  const float* __restrict__ Wiq, const float* __restrict__ biq,
                  const float* __restrict__ Wik, const float* __restrict__ bik,
                  const float* __restrict__ Wiv, const float* __restrict__ biv,
                  const float* __restrict__ Wo,  const float* __restrict__ bo,
                  const float* __restrict__ W_O,
                  const float* __restrict__ W_val, const float* __restrict__ b_val,
                  const float* __restrict__ W_adv, const float* __restrict__ b_adv,
                  float* __restrict__ out)
{
    extern __shared__ char gs[];
    __shared__ unsigned s_sense;
    __shared__ int s_sn;

    const int tid = threadIdx.x;
    const int bx  = blockIdx.x;
    const int wid = tid >> 5, lane = tid & 31;
    const int wm = wid & 3, wn = wid >> 2;
    const int g = lane >> 2, tg = lane & 3;
    const unsigned gs_u32 = su32(gs);
    if (tid == 0) s_sense = g_bar_sense;
    __syncthreads();

    // =====================================================================
    // PHASE 0: 0..7 obs encode + action (32 agents each);
    //          8..16 head combine; 17 mask
    // =====================================================================
    if (bx < 8) {
        const int base = bx * 32;
        {
            const int ai = base + (tid >> 4);
            const int c  = tid & 15;
            float o = b_enc[c];
            for (int d = 0; d < HID; ++d)
                o += hid[ai * HID + d] * W_enc[d * 16 + c];
            ushortt h, l; split1(o, h, l);
            g_Cb[0][ai * DD + c] = h;
            g_Cb[1][ai * DD + c] = l;
        }
        for (int idx = tid; idx < 32 * 32; idx += NTH) {
            const int ai = base + (idx >> 5), c4 = (idx & 31) * 4;
            float4 v = *(const float4*)&act[ai * HID + c4];
            unsigned h0, l0, h1, l1;
            split2(v.x, v.y, h0, l0);
            split2(v.z, v.w, h1, l1);
            const int o = ai * DD + 16 + c4;
            *(uint2*)&g_Cb[0][o] = make_uint2(h0, h1);
            *(uint2*)&g_Cb[1][o] = make_uint2(l0, l1);
        }
    } else if (bx < 17) {
        const int part = bx - 8;
        float* W2 = (float*)gs;   // 576*6 floats
        for (int r = tid; r < EE; r += NTH) {
            float a[6] = {};
            for (int k = 0; k < DD; ++k) {
                const float w = W_O[r * DD + k];
                a[0] += w * W_val[k];
#pragma unroll
                for (int j = 0; j < ACT; ++j) a[1 + j] += w * W_adv[k * ACT + j];
            }
#pragma unroll
            for (int j = 0; j < 6; ++j) W2[r * 6 + j] = a[j];
        }
        __syncthreads();
        {
            const int e  = part * 64 + (tid >> 3);
            const int f0 = (tid & 7) * 72;
            float a[6] = {};
            for (int f = f0; f < f0 + 72; ++f) {
                const float w = Wo[e * EE + f];
#pragma unroll
                for (int j = 0; j < 6; ++j) a[j] += w * W2[f * 6 + j];
            }
#pragma unroll
            for (int j = 0; j < 6; ++j) {
                a[j] += __shfl_xor_sync(0xffffffffu, a[j], 1);
                a[j] += __shfl_xor_sync(0xffffffffu, a[j], 2);
                a[j] += __shfl_xor_sync(0xffffffffu, a[j], 4);
            }
            if ((tid & 7) == 0) {
#pragma unroll
                for (int j = 0; j < 6; ++j) g_Wfin[e * 6 + j] = a[j];
            }
        }
        if (part == 0 && tid < 6) {
            float s = 0.f;
            for (int f = 0; f < EE; ++f) s += bo[f] * W2[f * 6 + tid];
            g_bfin[tid] = s;
        }
    } else if (bx == 17) {
        int* px = (int*)gs; int* py = px + NA;
        if (tid < NA) { px[tid] = state[2 * tid]; py[tid] = state[2 * tid + 1]; }
        __syncthreads();
        if (tid < NA) {
            unsigned wb[8] = {0, 0, 0, 0, 0, 0, 0, 0};
            const int xi = px[tid], yi = py[tid];
            for (int j = tid + 1; j < NA; ++j) {
                const int dx = abs(xi - px[j]);
                const int dy = abs(yi - py[j]);
                if (dx <= OBS_RX && dy <= OBS_RY) wb[j >> 5] |= (1u << (j & 31));
            }
#pragma unroll
            for (int q = 0; q < 8; ++q) g_mask[tid * 8 + q] = wb[q];
        }
    }
    GRID_BAR();

    // =====================================================================
    // PHASE B1: P(z) = C @ Wz + bz   (54 jobs: 3z x 2m x 9n, K=144)
    // =====================================================================
    if (bx < 54) {
        const int z  = bx / 18, r = bx % 18;
        const int m0 = (r / 9) * 128, n0 = (r % 9) * 64;
        const float* Wz = (z == 0) ? Wq : (z == 1) ? Wk : Wv;
        const float* bz = (z == 0) ? bq : (z == 1) ? bk : bv;
        float acc[2][2][4] = {};
        run_tile_w(&g_Cb[0][0] + m0 * DD, &g_Cb[1][0] + m0 * DD, DD,
                   Wz, EE, n0, DD, gs, gs_u32, tid, acc);
#pragma unroll
        for (int i = 0; i < 2; ++i) {
            const int row = m0 + wm * 32 + i * 16 + g;
#pragma unroll
            for (int j = 0; j < 2; ++j) {
                const int col = n0 + wn * 16 + j * 8 + 2 * tg;
                const float b0 = bz[col], b1 = bz[col + 1];
                unsigned h, l;
                split2(acc[i][j][0] + b0, acc[i][j][1] + b1, h, l);
                *(unsigned*)&g_Pb[0][z][row * EE + col] = h;
                *(unsigned*)&g_Pb[1][z][row * EE + col] = l;
                split2(acc[i][j][2] + b0, acc[i][j][3] + b1, h, l);
                *(unsigned*)&g_Pb[0][z][(row + 8) * EE + col] = h;
                *(unsigned*)&g_Pb[1][z][(row + 8) * EE + col] = l;
            }
        }
    }
    GRID_BAR();

    // =====================================================================
    // PHASE B2: qkv(z) = P(z) @ Wiz + biz   (54 jobs, K=576)
    // =====================================================================
    if (bx < 54) {
        const int z  = bx / 18, r = bx % 18;
        const int m0 = (r / 9) * 128, n0 = (r % 9) * 64;
        const float* Wiz = (z == 0) ? Wiq : (z == 1) ? Wik : Wiv;
        const float* biz = (z == 0) ? biq : (z == 1) ? bik : biv;
        float acc[2][2][4] = {};
        run_tile_w(&g_Pb[0][z][0] + m0 * EE, &g_Pb[1][z][0] + m0 * EE, EE,
                   Wiz, EE, n0, EE, gs, gs_u32, tid, acc);
#pragma unroll
        for (int i = 0; i < 2; ++i) {
            const int row = m0 + wm * 32 + i * 16 + g;
#pragma unroll
            for (int j = 0; j < 2; ++j) {
                const int col = n0 + wn * 16 + j * 8 + 2 * tg;
                const float b0 = biz[col], b1 = biz[col + 1];
                const float v0 = acc[i][j][0] + b0, v1 = acc[i][j][1] + b1;
                const float v2 = acc[i][j][2] + b0, v3 = acc[i][j][3] + b1;
                if (z < 2) {
                    unsigned h, l;
                    split2(v0, v1, h, l);
                    *(unsigned*)&g_Qb[0][z][row * EE + col] = h;
                    *(unsigned*)&g_Qb[1][z][row * EE + col] = l;
                    split2(v2, v3, h, l);
                    *(unsigned*)&g_Qb[0][z][(row + 8) * EE + col] = h;
                    *(unsigned*)&g_Qb[1][z][(row + 8) * EE + col] = l;
                } else {
                    *(float2*)&g_Qv[row * EE + col]       = make_float2(v0, v1);
                    *(float2*)&g_Qv[(row + 8) * EE + col] = make_float2(v2, v3);
                }
            }
        }
    }
    GRID_BAR();

    // =====================================================================
    // PHASE S: S[h] = (1/12) q2_h @ k2_h^T  (32 jobs: 4h x 2m x 4n, K=144)
    // =====================================================================
    if (bx < 32) {
        const int h  = bx / 8, r = bx % 8;
        const int m0 = (r / 4) * 128, n0 = (r % 4) * 64;
        float acc[2][2][4] = {};
        run_tile_a(&g_Qb[0][0][0] + m0 * EE + h * HDH, &g_Qb[1][0][0] + m0 * EE + h * HDH, EE,
                   &g_Qb[0][1][0] + n0 * EE + h * HDH, &g_Qb[1][1][0] + n0 * EE + h * HDH, EE,
                   HDH, gs, gs_u32, tid, acc);
        float* Cd = g_S + h * NA * NA;
#pragma unroll
        for (int i = 0; i < 2; ++i) {
            const int row = m0 + wm * 32 + i * 16 + g;
#pragma unroll
            for (int j = 0; j < 2; ++j) {
                const int col = n0 + wn * 16 + j * 8 + 2 * tg;
                *(float2*)&Cd[row * NA + col] =
                    make_float2(acc[i][j][0] * (1.f / 12.f), acc[i][j][1] * (1.f / 12.f));
                *(float2*)&Cd[(row + 8) * NA + col] =
                    make_float2(acc[i][j][2] * (1.f / 12.f), acc[i][j][3] * (1.f / 12.f));
            }
        }
    }
    GRID_BAR();

    // =====================================================================
    // PHASE DE: per-agent masked softmax-sum + context + final head
    // =====================================================================
    {
        float* w   = (float*)gs;             // NH*NA floats
        int*   Jl  = (int*)(gs + 4096);      // NA ints
        float* red = (float*)(gs + 5120);    // 6 floats
        for (int i = bx; i < NA; i += NB) {
            for (int q = tid; q < NH * NA; q += NTH) w[q] = 0.f;
            if (tid < 6) red[tid] = 0.f;
            if (tid == 0) {
                int n = 0;
                for (int q = 0; q < 8; ++q) {
                    unsigned bits = g_mask[i * 8 + q];
                    while (bits) {
                        const int b = __ffs(bits) - 1;
                        Jl[n++] = q * 32 + b;
                        bits &= bits - 1;
                    }
                }
                s_sn = n;
            }
            __syncthreads();
            const int n = s_sn;
            float a6[6] = {};
            if (n > 0) {
                for (int p = tid; p < NH * n; p += NTH) {
                    const int h  = p & 3;
                    const int jj = Jl[p >> 2];
                    const float* row = g_S + h * NA * NA + jj * NA;
                    float m = -1e30f;
                    for (int q = 0; q < n; ++q) m = fmaxf(m, row[Jl[q]]);
                    float sum = 0.f;
                    for (int q = 0; q < n; ++q) sum += expf(row[Jl[q]] - m);
                    const float inv = 1.f / sum;
                    for (int q = 0; q < n; ++q)
                        atomicAdd(&w[h * NA + q], expf(row[Jl[q]] - m) * inv);
                }
                __syncthreads();
                for (int e = tid; e < EE; e += NTH) {
                    const int h = e / HDH;
                    float G = 0.f;
                    for (int q = 0; q < n; ++q)
                        G += w[h * NA + q] * g_Qv[Jl[q] * EE + e];
                    const float* Wr = g_Wfin + e * 6;
#pragma unroll
                    for (int j = 0; j < 6; ++j) a6[j] += G * Wr[j];
                }
            }
#pragma unroll
            for (int j = 0; j < 6; ++j)
#pragma unroll
                for (int o = 16; o > 0; o >>= 1)
                    a6[j] += __shfl_xor_sync(0xffffffffu, a6[j], o);
            if (lane == 0) {
#pragma unroll
                for (int j = 0; j < 6; ++j) atomicAdd(&red[j], a6[j]);
            }
            __syncthreads();
            if (tid == 0) {
                const float c = (float)n;
                const float V = red[0] + c * g_bfin[0] + b_val[0];
                float A[ACT], mean = 0.f;
#pragma unroll
                for (int j = 0; j < ACT; ++j) {
                    A[j] = red[1 + j] + c * g_bfin[1 + j] + b_adv[j];
                    mean += A[j];
                }
                mean *= (1.f / ACT);
#pragma unroll
                for (int j = 0; j < ACT; ++j) out[i * ACT + j] = V + A[j] - mean;
            }
            __syncthreads();
        }
    }
}

// ---------------------------------------------------------------------------
extern "C" void kernel_launch(void* const* d_in, const int* in_sizes, int n_in,
                              void* d_out, int out_size)
{
    const float *hid, *act, *W_enc, *b_enc, *Wq, *bq, *Wk, *bk, *Wv, *bv;
    const float *Wiq, *biq, *Wik, *bik, *Wiv, *biv, *Wo, *bo, *W_O;
    const float *W_val, *b_val, *W_adv, *b_adv;
    const int* state;

    if (n_in >= 3 && in_sizes[2] == 512) {
        hid   = (const float*)d_in[0];  act  = (const float*)d_in[1];
        state = (const int*)  d_in[2];
        W_enc = (const float*)d_in[3];  b_enc = (const float*)d_in[4];
        Wq  = (const float*)d_in[5];    bq  = (const float*)d_in[6];
        Wk  = (const float*)d_in[7];    bk  = (const float*)d_in[8];
        Wv  = (const float*)d_in[9];    bv  = (const float*)d_in[10];
        Wiq = (const float*)d_in[11];   biq = (const float*)d_in[12];
        Wik = (const float*)d_in[13];   bik = (const float*)d_in[14];
        Wiv = (const float*)d_in[15];   biv = (const float*)d_in[16];
        Wo  = (const float*)d_in[17];   bo  = (const float*)d_in[18];
        W_O = (const float*)d_in[19];
        W_val = (const float*)d_in[20]; b_val = (const float*)d_in[21];
        W_adv = (const float*)d_in[22]; b_adv = (const float*)d_in[23];
    } else {
        hid   = (const float*)d_in[0];  act  = (const float*)d_in[1];
        W_enc = (const float*)d_in[2];  b_enc = (const float*)d_in[3];
        Wq  = (const float*)d_in[4];    bq  = (const float*)d_in[5];
        Wk  = (const float*)d_in[6];    bk  = (const float*)d_in[7];
        Wv  = (const float*)d_in[8];    bv  = (const float*)d_in[9];
        Wiq = (const float*)d_in[10];   biq = (const float*)d_in[11];
        Wik = (const float*)d_in[12];   bik = (const float*)d_in[13];
        Wiv = (const float*)d_in[14];   biv = (const float*)d_in[15];
        Wo  = (const float*)d_in[16];   bo  = (const float*)d_in[17];
        W_O = (const float*)d_in[18];
        W_val = (const float*)d_in[19]; b_val = (const float*)d_in[20];
        W_adv = (const float*)d_in[21]; b_adv = (const float*)d_in[22];
        state = (const int*)  d_in[23];
    }

    static bool attr_set = false;
    if (!attr_set) {
        cudaFuncSetAttribute(fused_kernel,
                             cudaFuncAttributeMaxDynamicSharedMemorySize, SMEM_DYN);
        attr_set = true;
    }

    fused_kernel<<<NB, NTH, SMEM_DYN>>>(hid, act, state, W_enc, b_enc,
                                        Wq, bq, Wk, bk, Wv, bv,
                                        Wiq, biq, Wik, bik, Wiv, biv,
                                        Wo, bo, W_O, W_val, b_val, W_adv, b_adv,
                                        (float*)d_out);
}

// round 12
// speedup vs baseline: 1.4596x; 1.0853x over previous
#include <cuda_runtime.h>
#include <cuda_bf16.h>
#include <math.h>
#include <stdint.h>

typedef unsigned short ushortt;

// ---------------------------------------------------------------------------
#define NA   256
#define HID  128
#define ACT  5
#define NH   4
#define DD   144
#define EE   576
#define HDH  144
#define OBS_RX 4
#define OBS_RY 2
#define NTH  512          // GEMM kernels: 16 warps

#define PITCHU 28
#define BPITCH 144
#define CHUNK  48
#define OFF_AL 14336
#define OFF_BH 28672
#define OFF_BL 35840
#define BUF_BYTES 43008
#define SMEM_DYN  (2 * BUF_BYTES)   // 86016

// ---------------------------------------------------------------------------
__device__ __align__(16) ushortt g_Cb[2][NA * DD];
__device__ __align__(16) ushortt g_Pb[2][3][NA * EE];
__device__ __align__(16) ushortt g_Qb[2][2][NA * EE];
__device__ __align__(16) float   g_Qv[NA * EE];
__device__ __align__(16) float   g_S[NH * NA * NA];
__device__ unsigned g_mask[NA * 8];
__device__ __align__(16) float   g_Wfin[EE * 6];
__device__ float    g_bfin[6];

// ---------------------------------------------------------------------------
__device__ __forceinline__ unsigned su32(const void* p) {
    unsigned a;
    asm("{ .reg .u64 t; cvta.to.shared.u64 t, %1; cvt.u32.u64 %0, t; }"
        : "=r"(a) : "l"(p));
    return a;
}
__device__ __forceinline__ void cpa16(unsigned s, const void* g) {
    asm volatile("cp.async.cg.shared.global [%0], [%1], 16;" :: "r"(s), "l"(g));
}
#define CPA_COMMIT() asm volatile("cp.async.commit_group;" ::: "memory")
#define CPA_WAIT0()  asm volatile("cp.async.wait_group 0;" ::: "memory")

__device__ __forceinline__ void mma16816(float c[4],
    unsigned a0, unsigned a1, unsigned a2, unsigned a3,
    unsigned b0, unsigned b1)
{
    asm volatile(
        "mma.sync.aligned.m16n8k16.row.col.f32.bf16.bf16.f32 "
        "{%0,%1,%2,%3}, {%4,%5,%6,%7}, {%8,%9}, {%0,%1,%2,%3};"
        : "+f"(c[0]), "+f"(c[1]), "+f"(c[2]), "+f"(c[3])
        : "r"(a0), "r"(a1), "r"(a2), "r"(a3), "r"(b0), "r"(b1));
}
__device__ __forceinline__ void ldmx4t(unsigned& r0, unsigned& r1,
                                       unsigned& r2, unsigned& r3, unsigned a)
{
    asm volatile("ldmatrix.sync.aligned.m8n8.x4.trans.shared.b16 {%0,%1,%2,%3}, [%4];"
                 : "=r"(r0), "=r"(r1), "=r"(r2), "=r"(r3) : "r"(a));
}

__device__ __forceinline__ void split1(float v, ushortt& h, ushortt& l) {
    __nv_bfloat16 hb = __float2bfloat16(v);
    float r = v - __bfloat162float(hb);
    __nv_bfloat16 lb = __float2bfloat16(r);
    h = __bfloat16_as_ushort(hb);
    l = __bfloat16_as_ushort(lb);
}
__device__ __forceinline__ void split2(float v0, float v1, unsigned& h, unsigned& l) {
    ushortt h0, l0, h1, l1;
    split1(v0, h0, l0); split1(v1, h1, l1);
    h = ((unsigned)h1 << 16) | h0;
    l = ((unsigned)l1 << 16) | l0;
}

// ---------------------------------------------------------------------------
__device__ __forceinline__ void stageA_cp(const ushortt* __restrict__ AH,
                                          const ushortt* __restrict__ AL,
                                          int lda, int k0, unsigned sbuf, int tid)
{
    for (int idx = tid; idx < 768; idx += NTH) {
        const int r = idx / 6, cc = idx % 6;
        const unsigned d = sbuf + r * 112 + cc * 16;
        const int go = r * lda + k0 + cc * 8;
        cpa16(d,          AH + go);
        cpa16(d + OFF_AL, AL + go);
    }
}
__device__ __forceinline__ void stageB_cp(const ushortt* __restrict__ BH,
                                          const ushortt* __restrict__ BL,
                                          int ldb, int k0, unsigned sbuf, int tid)
{
    for (int idx = tid; idx < 384; idx += NTH) {
        const int r = idx / 6, cc = idx % 6;
        const unsigned d = sbuf + OFF_BH + r * 112 + cc * 16;
        const int go = r * ldb + k0 + cc * 8;
        cpa16(d,                     BH + go);
        cpa16(d + (OFF_BL - OFF_BH), BL + go);
    }
}
__device__ __forceinline__ void ldgB_w(const float* __restrict__ W, int ldw,
                                       int n0, int k0, float4 br[2], int tid)
{
#pragma unroll
    for (int t = 0; t < 2; ++t) {
        const int idx = tid + t * NTH;
        if (idx < 768) {
            const int r = idx >> 4, c4 = (idx & 15) * 4;
            br[t] = *(const float4*)&W[(size_t)(k0 + r) * ldw + n0 + c4];
        }
    }
}
__device__ __forceinline__ void stsB_w(const float4 br[2], char* gsbuf, int tid)
{
#pragma unroll
    for (int t = 0; t < 2; ++t) {
        const int idx = tid + t * NTH;
        if (idx < 768) {
            const int r = idx >> 4, c4 = (idx & 15) * 4;
            unsigned h0, l0, h1, l1;
            split2(br[t].x, br[t].y, h0, l0);
            split2(br[t].z, br[t].w, h1, l1);
            char* p = gsbuf + OFF_BH + r * BPITCH + c4 * 2;
            *(uint2*)p = make_uint2(h0, h1);
            *(uint2*)(p + (OFF_BL - OFF_BH)) = make_uint2(l0, l1);
        }
    }
}

__device__ __forceinline__ void load_afrag(const char* buf, int wm, int g, int tg,
                                           int kk, unsigned ah[2][4], unsigned al[2][4])
{
    const unsigned* AH = (const unsigned*)buf;
    const unsigned* AL = (const unsigned*)(buf + OFF_AL);
    const int kc = kk * 8 + tg;
#pragma unroll
    for (int i = 0; i < 2; ++i) {
        const int r0 = (wm * 32 + i * 16 + g) * PITCHU;
        const int r1 = r0 + 8 * PITCHU;
        ah[i][0] = AH[r0 + kc];     ah[i][1] = AH[r1 + kc];
        ah[i][2] = AH[r0 + kc + 4]; ah[i][3] = AH[r1 + kc + 4];
        al[i][0] = AL[r0 + kc];     al[i][1] = AL[r1 + kc];
        al[i][2] = AL[r0 + kc + 4]; al[i][3] = AL[r1 + kc + 4];
    }
}

__device__ __forceinline__ void mma_chunk_a(const char* buf, int wm, int wn,
                                            int g, int tg, float acc[2][2][4])
{
    const unsigned* BH = (const unsigned*)(buf + OFF_BH);
    const unsigned* BL = (const unsigned*)(buf + OFF_BL);
#pragma unroll
    for (int kk = 0; kk < 3; ++kk) {
        unsigned ah[2][4], al[2][4];
        load_afrag(buf, wm, g, tg, kk, ah, al);
        const int kc = kk * 8 + tg;
#pragma unroll
        for (int j = 0; j < 2; ++j) {
            const int nrow = (wn * 16 + j * 8 + g) * PITCHU;
            const unsigned bh0 = BH[nrow + kc], bh1 = BH[nrow + kc + 4];
            const unsigned bl0 = BL[nrow + kc], bl1 = BL[nrow + kc + 4];
#pragma unroll
            for (int i = 0; i < 2; ++i) {
                mma16816(acc[i][j], ah[i][0], ah[i][1], ah[i][2], ah[i][3], bh0, bh1);
                mma16816(acc[i][j], ah[i][0], ah[i][1], ah[i][2], ah[i][3], bl0, bl1);
                mma16816(acc[i][j], al[i][0], al[i][1], al[i][2], al[i][3], bh0, bh1);
            }
        }
    }
}

__device__ __forceinline__ void mma_chunk_w(const char* buf, unsigned bufu,
                                            int wm, int g, int tg,
                                            int krow_off, int joff_b,
                                            float acc[2][2][4])
{
#pragma unroll
    for (int kk = 0; kk < 3; ++kk) {
        unsigned ah[2][4], al[2][4];
        load_afrag(buf, wm, g, tg, kk, ah, al);
        const unsigned ba = bufu + OFF_BH +
            (unsigned)((kk * 16 + krow_off) * BPITCH) + joff_b;
        unsigned bh0, bh1, bh2, bh3, bl0, bl1, bl2, bl3;
        ldmx4t(bh0, bh1, bh2, bh3, ba);
        ldmx4t(bl0, bl1, bl2, bl3, ba + (OFF_BL - OFF_BH));
#pragma unroll
        for (int i = 0; i < 2; ++i) {
            mma16816(acc[i][0], ah[i][0], ah[i][1], ah[i][2], ah[i][3], bh0, bh1);
            mma16816(acc[i][0], ah[i][0], ah[i][1], ah[i][2], ah[i][3], bl0, bl1);
            mma16816(acc[i][0], al[i][0], al[i][1], al[i][2], al[i][3], bh0, bh1);
            mma16816(acc[i][1], ah[i][0], ah[i][1], ah[i][2], ah[i][3], bh2, bh3);
            mma16816(acc[i][1], ah[i][0], ah[i][1], ah[i][2], ah[i][3], bl2, bl3);
            mma16816(acc[i][1], al[i][0], al[i][1], al[i][2], al[i][3], bh2, bh3);
        }
    }
}

__device__ __forceinline__ void run_tile_a(
    const ushortt* AH, const ushortt* AL, int lda,
    const ushortt* BH, const ushortt* BL, int ldb,
    int K, char* gs, unsigned gs_u32, int tid, float acc[2][2][4])
{
    const int wm = (tid >> 5) & 3, wn = tid >> 7;
    const int g = (tid & 31) >> 2, tg = tid & 3;
    const int nc = K / CHUNK;
    stageA_cp(AH, AL, lda, 0, gs_u32, tid);
    stageB_cp(BH, BL, ldb, 0, gs_u32, tid);
    CPA_COMMIT();
    for (int c = 0; c < nc; ++c) {
        CPA_WAIT0();
        __syncthreads();
        if (c + 1 < nc) {
            const unsigned nb = gs_u32 + ((c + 1) & 1) * BUF_BYTES;
            stageA_cp(AH, AL, lda, (c + 1) * CHUNK, nb, tid);
            stageB_cp(BH, BL, ldb, (c + 1) * CHUNK, nb, tid);
            CPA_COMMIT();
        }
        mma_chunk_a(gs + (c & 1) * BUF_BYTES, wm, wn, g, tg, acc);
        __syncthreads();
    }
}

__device__ __forceinline__ void run_tile_w(
    const ushortt* AH, const ushortt* AL, int lda,
    const float* W, int ldw, int n0,
    int K, char* gs, unsigned gs_u32, int tid, float acc[2][2][4])
{
    const int lane = tid & 31;
    const int wm = (tid >> 5) & 3, wn = tid >> 7;
    const int g = lane >> 2, tg = lane & 3;
    const int krow_off = ((lane >> 3) & 1) * 8 + (lane & 7);
    const int joff_b = (wn * 16 + ((lane >> 4) & 1) * 8) * 2;

    float4 br[2];
    const int nc = K / CHUNK;
    stageA_cp(AH, AL, lda, 0, gs_u32, tid);
    CPA_COMMIT();
    ldgB_w(W, ldw, n0, 0, br, tid);
    stsB_w(br, gs, tid);
    for (int c = 0; c < nc; ++c) {
        CPA_WAIT0();
        __syncthreads();
        if (c + 1 < nc) {
            stageA_cp(AH, AL, lda, (c + 1) * CHUNK,
                      gs_u32 + ((c + 1) & 1) * BUF_BYTES, tid);
            CPA_COMMIT();
            ldgB_w(W, ldw, n0, (c + 1) * CHUNK, br, tid);
        }
        mma_chunk_w(gs + (c & 1) * BUF_BYTES, gs_u32 + (c & 1) * BUF_BYTES,
                    wm, g, tg, krow_off, joff_b, acc);
        if (c + 1 < nc) stsB_w(br, gs + ((c + 1) & 1) * BUF_BYTES, tid);
        __syncthreads();
    }
}

// ---------------------------------------------------------------------------
// LAUNCH 1: setup (obs encode, head combine, mask). 18 blocks x 512.
// ---------------------------------------------------------------------------
__global__ __launch_bounds__(NTH)
void k_setup(const float* __restrict__ hid, const float* __restrict__ act,
             const int* __restrict__ state,
             const float* __restrict__ W_enc, const float* __restrict__ b_enc,
             const float* __restrict__ Wo, const float* __restrict__ bo,
             const float* __restrict__ W_O,
             const float* __restrict__ W_val, const float* __restrict__ W_adv)
{
    __shared__ float W2[EE * 6];       // also reused as px/py for mask block
    const int tid = threadIdx.x;
    const int bx  = blockIdx.x;

    if (bx < 8) {
        const int base = bx * 32;
        {
            const int ai = base + (tid >> 4);
            const int c  = tid & 15;
            float o = b_enc[c];
            for (int d = 0; d < HID; ++d)
                o += hid[ai * HID + d] * W_enc[d * 16 + c];
            ushortt h, l; split1(o, h, l);
            g_Cb[0][ai * DD + c] = h;
            g_Cb[1][ai * DD + c] = l;
        }
        for (int idx = tid; idx < 32 * 32; idx += NTH) {
            const int ai = base + (idx >> 5), c4 = (idx & 31) * 4;
            float4 v = *(const float4*)&act[ai * HID + c4];
            unsigned h0, l0, h1, l1;
            split2(v.x, v.y, h0, l0);
            split2(v.z, v.w, h1, l1);
            const int o = ai * DD + 16 + c4;
            *(uint2*)&g_Cb[0][o] = make_uint2(h0, h1);
            *(uint2*)&g_Cb[1][o] = make_uint2(l0, l1);
        }
    } else if (bx < 17) {
        const int part = bx - 8;
        for (int r = tid; r < EE; r += NTH) {
            float a[6] = {};
            for (int k = 0; k < DD; ++k) {
                const float w = W_O[r * DD + k];
                a[0] += w * W_val[k];
#pragma unroll
                for (int j = 0; j < ACT; ++j) a[1 + j] += w * W_adv[k * ACT + j];
            }
#pragma unroll
            for (int j = 0; j < 6; ++j) W2[r * 6 + j] = a[j];
        }
        __syncthreads();
        {
            const int e  = part * 64 + (tid >> 3);
            const int f0 = (tid & 7) * 72;
            float a[6] = {};
            for (int f = f0; f < f0 + 72; ++f) {
                const float w = Wo[e * EE + f];
#pragma unroll
                for (int j = 0; j < 6; ++j) a[j] += w * W2[f * 6 + j];
            }
#pragma unroll
            for (int j = 0; j < 6; ++j) {
                a[j] += __shfl_xor_sync(0xffffffffu, a[j], 1);
                a[j] += __shfl_xor_sync(0xffffffffu, a[j], 2);
                a[j] += __shfl_xor_sync(0xffffffffu, a[j], 4);
            }
            if ((tid & 7) == 0) {
#pragma unroll
                for (int j = 0; j < 6; ++j) g_Wfin[e * 6 + j] = a[j];
            }
        }
        if (part == 0 && tid < 6) {
            float s = 0.f;
            for (int f = 0; f < EE; ++f) s += bo[f] * W2[f * 6 + tid];
            g_bfin[tid] = s;
        }
    } else {
        int* px = (int*)W2; int* py = px + NA;
        if (tid < NA) { px[tid] = state[2 * tid]; py[tid] = state[2 * tid + 1]; }
        __syncthreads();
        if (tid < NA) {
            unsigned wb[8] = {0, 0, 0, 0, 0, 0, 0, 0};
            const int xi = px[tid], yi = py[tid];
            for (int j = tid + 1; j < NA; ++j) {
                const int dx = abs(xi - px[j]);
                const int dy = abs(yi - py[j]);
                if (dx <= OBS_RX && dy <= OBS_RY) wb[j >> 5] |= (1u << (j & 31));
            }
#pragma unroll
            for (int q = 0; q < 8; ++q) g_mask[tid * 8 + q] = wb[q];
        }
    }
}

// ---------------------------------------------------------------------------
// LAUNCH 2: B1  P(z) = C @ Wz + bz   (54 blocks x 512, K=144)
// ---------------------------------------------------------------------------
__global__ __launch_bounds__(NTH)
void k_b1(const float* __restrict__ Wq, const float* __restrict__ bq,
          const float* __restrict__ Wk, const float* __restrict__ bk,
          const float* __restrict__ Wv, const float* __restrict__ bv)
{
    extern __shared__ char gs[];
    const int tid = threadIdx.x;
    const int bx  = blockIdx.x;
    const int wid = tid >> 5, lane = tid & 31;
    const int wm = wid & 3, wn = wid >> 2;
    const int g = lane >> 2, tg = lane & 3;
    const unsigned gs_u32 = su32(gs);

    const int z  = bx / 18, r = bx % 18;
    const int m0 = (r / 9) * 128, n0 = (r % 9) * 64;
    const float* Wz = (z == 0) ? Wq : (z == 1) ? Wk : Wv;
    const float* bz = (z == 0) ? bq : (z == 1) ? bk : bv;
    float acc[2][2][4] = {};
    run_tile_w(&g_Cb[0][0] + m0 * DD, &g_Cb[1][0] + m0 * DD, DD,
               Wz, EE, n0, DD, gs, gs_u32, tid, acc);
#pragma unroll
    for (int i = 0; i < 2; ++i) {
        const int row = m0 + wm * 32 + i * 16 + g;
#pragma unroll
        for (int j = 0; j < 2; ++j) {
            const int col = n0 + wn * 16 + j * 8 + 2 * tg;
            const float b0 = bz[col], b1 = bz[col + 1];
            unsigned h, l;
            split2(acc[i][j][0] + b0, acc[i][j][1] + b1, h, l);
            *(unsigned*)&g_Pb[0][z][row * EE + col] = h;
            *(unsigned*)&g_Pb[1][z][row * EE + col] = l;
            split2(acc[i][j][2] + b0, acc[i][j][3] + b1, h, l);
            *(unsigned*)&g_Pb[0][z][(row + 8) * EE + col] = h;
            *(unsigned*)&g_Pb[1][z][(row + 8) * EE + col] = l;
        }
    }
}

// ---------------------------------------------------------------------------
// LAUNCH 3: B2  qkv(z) = P(z) @ Wiz + biz  (54 blocks x 512, K=576)
// ---------------------------------------------------------------------------
__global__ __launch_bounds__(NTH)
void k_b2(const float* __restrict__ Wiq, const float* __restrict__ biq,
          const float* __restrict__ Wik, const float* __restrict__ bik,
          const float* __restrict__ Wiv, const float* __restrict__ biv)
{
    extern __shared__ char gs[];
    const int tid = threadIdx.x;
    const int bx  = blockIdx.x;
    const int wid = tid >> 5, lane = tid & 31;
    const int wm = wid & 3, wn = wid >> 2;
    const int g = lane >> 2, tg = lane & 3;
    const unsigned gs_u32 = su32(gs);

    const int z  = bx / 18, r = bx % 18;
    const int m0 = (r / 9) * 128, n0 = (r % 9) * 64;
    const float* Wiz = (z == 0) ? Wiq : (z == 1) ? Wik : Wiv;
    const float* biz = (z == 0) ? biq : (z == 1) ? bik : biv;
    float acc[2][2][4] = {};
    run_tile_w(&g_Pb[0][z][0] + m0 * EE, &g_Pb[1][z][0] + m0 * EE, EE,
               Wiz, EE, n0, EE, gs, gs_u32, tid, acc);
#pragma unroll
    for (int i = 0; i < 2; ++i) {
        const int row = m0 + wm * 32 + i * 16 + g;
#pragma unroll
        for (int j = 0; j < 2; ++j) {
            const int col = n0 + wn * 16 + j * 8 + 2 * tg;
            const float b0 = biz[col], b1 = biz[col + 1];
            const float v0 = acc[i][j][0] + b0, v1 = acc[i][j][1] + b1;
            const float v2 = acc[i][j][2] + b0, v3 = acc[i][j][3] + b1;
            if (z < 2) {
                unsigned h, l;
                split2(v0, v1, h, l);
                *(unsigned*)&g_Qb[0][z][row * EE + col] = h;
                *(unsigned*)&g_Qb[1][z][row * EE + col] = l;
                split2(v2, v3, h, l);
                *(unsigned*)&g_Qb[0][z][(row + 8) * EE + col] = h;
                *(unsigned*)&g_Qb[1][z][(row + 8) * EE + col] = l;
            } else {
                *(float2*)&g_Qv[row * EE + col]       = make_float2(v0, v1);
                *(float2*)&g_Qv[(row + 8) * EE + col] = make_float2(v2, v3);
            }
        }
    }
}

// ---------------------------------------------------------------------------
// LAUNCH 4: S[h] = (1/12) q2_h @ k2_h^T  (32 blocks x 512, K=144)
// ---------------------------------------------------------------------------
__global__ __launch_bounds__(NTH)
void k_s()
{
    extern __shared__ char gs[];
    const int tid = threadIdx.x;
    const int bx  = blockIdx.x;
    const int wid = tid >> 5, lane = tid & 31;
    const int wm = wid & 3, wn = wid >> 2;
    const int g = lane >> 2, tg = lane & 3;
    const unsigned gs_u32 = su32(gs);

    const int h  = bx / 8, r = bx % 8;
    const int m0 = (r / 4) * 128, n0 = (r % 4) * 64;
    float acc[2][2][4] = {};
    run_tile_a(&g_Qb[0][0][0] + m0 * EE + h * HDH, &g_Qb[1][0][0] + m0 * EE + h * HDH, EE,
               &g_Qb[0][1][0] + n0 * EE + h * HDH, &g_Qb[1][1][0] + n0 * EE + h * HDH, EE,
               HDH, gs, gs_u32, tid, acc);
    float* Cd = g_S + h * NA * NA;
#pragma unroll
    for (int i = 0; i < 2; ++i) {
        const int row = m0 + wm * 32 + i * 16 + g;
#pragma unroll
        for (int j = 0; j < 2; ++j) {
            const int col = n0 + wn * 16 + j * 8 + 2 * tg;
            *(float2*)&Cd[row * NA + col] =
                make_float2(acc[i][j][0] * (1.f / 12.f), acc[i][j][1] * (1.f / 12.f));
            *(float2*)&Cd[(row + 8) * NA + col] =
                make_float2(acc[i][j][2] * (1.f / 12.f), acc[i][j][3] * (1.f / 12.f));
        }
    }
}

// ---------------------------------------------------------------------------
// LAUNCH 5: per-agent masked softmax-sum + context + final head.
// 256 blocks (one per agent) x 256 threads.
// ---------------------------------------------------------------------------
#define DTH 256
__global__ __launch_bounds__(DTH)
void k_de(const float* __restrict__ b_val, const float* __restrict__ b_adv,
          float* __restrict__ out)
{
    __shared__ float w[NH * NA];
    __shared__ int   Jl[NA];
    __shared__ float red[6];
    __shared__ int   s_sn;

    const int tid  = threadIdx.x;
    const int lane = tid & 31;
    const int i    = blockIdx.x;

    for (int q = tid; q < NH * NA; q += DTH) w[q] = 0.f;
    if (tid < 6) red[tid] = 0.f;
    if (tid == 0) {
        int n = 0;
        for (int q = 0; q < 8; ++q) {
            unsigned bits = g_mask[i * 8 + q];
            while (bits) {
                const int b = __ffs(bits) - 1;
                Jl[n++] = q * 32 + b;
                bits &= bits - 1;
            }
        }
        s_sn = n;
    }
    __syncthreads();
    const int n = s_sn;
    float a6[6] = {};
    if (n > 0) {
        for (int p = tid; p < NH * n; p += DTH) {
            const int h  = p & 3;
            const int jj = Jl[p >> 2];
            const float* row = g_S + h * NA * NA + jj * NA;
            float m = -1e30f;
            for (int q = 0; q < n; ++q) m = fmaxf(m, row[Jl[q]]);
            float sum = 0.f;
            for (int q = 0; q < n; ++q) sum += expf(row[Jl[q]] - m);
            const float inv = 1.f / sum;
            for (int q = 0; q < n; ++q)
                atomicAdd(&w[h * NA + q], expf(row[Jl[q]] - m) * inv);
        }
        __syncthreads();
        for (int e = tid; e < EE; e += DTH) {
            const int h = e / HDH;
            float G = 0.f;
            for (int q = 0; q < n; ++q)
                G += w[h * NA + q] * g_Qv[Jl[q] * EE + e];
            const float* Wr = g_Wfin + e * 6;
#pragma unroll
            for (int j = 0; j < 6; ++j) a6[j] += G * Wr[j];
        }
    }
#pragma unroll
    for (int j = 0; j < 6; ++j)
#pragma unroll
        for (int o = 16; o > 0; o >>= 1)
            a6[j] += __shfl_xor_sync(0xffffffffu, a6[j], o);
    if (lane == 0) {
#pragma unroll
        for (int j = 0; j < 6; ++j) atomicAdd(&red[j], a6[j]);
    }
    __syncthreads();
    if (tid == 0) {
        const float c = (float)n;
        const float V = red[0] + c * g_bfin[0] + b_val[0];
        float A[ACT], mean = 0.f;
#pragma unroll
        for (int j = 0; j < ACT; ++j) {
            A[j] = red[1 + j] + c * g_bfin[1 + j] + b_adv[j];
            mean += A[j];
        }
        mean *= (1.f / ACT);
#pragma unroll
        for (int j = 0; j < ACT; ++j) out[i * ACT + j] = V + A[j] - mean;
    }
}

// ---------------------------------------------------------------------------
extern "C" void kernel_launch(void* const* d_in, const int* in_sizes, int n_in,
                              void* d_out, int out_size)
{
    const float *hid, *act, *W_enc, *b_enc, *Wq, *bq, *Wk, *bk, *Wv, *bv;
    const float *Wiq, *biq, *Wik, *bik, *Wiv, *biv, *Wo, *bo, *W_O;
    const float *W_val, *b_val, *W_adv, *b_adv;
    const int* state;

    if (n_in >= 3 && in_sizes[2] == 512) {
        hid   = (const float*)d_in[0];  act  = (const float*)d_in[1];
        state = (const int*)  d_in[2];
        W_enc = (const float*)d_in[3];  b_enc = (const float*)d_in[4];
        Wq  = (const float*)d_in[5];    bq  = (const float*)d_in[6];
        Wk  = (const float*)d_in[7];    bk  = (const float*)d_in[8];
        Wv  = (const float*)d_in[9];    bv  = (const float*)d_in[10];
        Wiq = (const float*)d_in[11];   biq = (const float*)d_in[12];
        Wik = (const float*)d_in[13];   bik = (const float*)d_in[14];
        Wiv = (const float*)d_in[15];   biv = (const float*)d_in[16];
        Wo  = (const float*)d_in[17];   bo  = (const float*)d_in[18];
        W_O = (const float*)d_in[19];
        W_val = (const float*)d_in[20]; b_val = (const float*)d_in[21];
        W_adv = (const float*)d_in[22]; b_adv = (const float*)d_in[23];
    } else {
        hid   = (const float*)d_in[0];  act  = (const float*)d_in[1];
        W_enc = (const float*)d_in[2];  b_enc = (const float*)d_in[3];
        Wq  = (const float*)d_in[4];    bq  = (const float*)d_in[5];
        Wk  = (const float*)d_in[6];    bk  = (const float*)d_in[7];
        Wv  = (const float*)d_in[8];    bv  = (const float*)d_in[9];
        Wiq = (const float*)d_in[10];   biq = (const float*)d_in[11];
        Wik = (const float*)d_in[12];   bik = (const float*)d_in[13];
        Wiv = (const float*)d_in[14];   biv = (const float*)d_in[15];
        Wo  = (const float*)d_in[16];   bo  = (const float*)d_in[17];
        W_O = (const float*)d_in[18];
        W_val = (const float*)d_in[19]; b_val = (const float*)d_in[20];
        W_adv = (const float*)d_in[21]; b_adv = (const float*)d_in[22];
        state = (const int*)  d_in[23];
    }

    static bool attr_set = false;
    if (!attr_set) {
        cudaFuncSetAttribute(k_b1, cudaFuncAttributeMaxDynamicSharedMemorySize, SMEM_DYN);
        cudaFuncSetAttribute(k_b2, cudaFuncAttributeMaxDynamicSharedMemorySize, SMEM_DYN);
        cudaFuncSetAttribute(k_s,  cudaFuncAttributeMaxDynamicSharedMemorySize, SMEM_DYN);
        attr_set = true;
    }

    k_setup<<<18, NTH>>>(hid, act, state, W_enc, b_enc, Wo, bo, W_O, W_val, W_adv);
    k_b1<<<54, NTH, SMEM_DYN>>>(Wq, bq, Wk, bk, Wv, bv);
    k_b2<<<54, NTH, SMEM_DYN>>>(Wiq, biq, Wik, bik, Wiv, biv);
    k_s<<<32, NTH, SMEM_DYN>>>();
    k_de<<<NA, DTH>>>(b_val, b_adv, (float*)d_out);
}

// round 13
// speedup vs baseline: 1.6220x; 1.1113x over previous
#include <cuda_runtime.h>
#include <cuda_bf16.h>
#include <math.h>
#include <stdint.h>

typedef unsigned short ushortt;

// ---------------------------------------------------------------------------
#define NA   256
#define HID  128
#define ACT  5
#define NH   4
#define DD   144
#define EE   576
#define HDH  144
#define OBS_RX 4
#define OBS_RY 2
#define NTH  512

#define PITCHU 28          // A / mode-a B row pitch in u32 (112B)
#define BPITCH 144         // mode-b B row pitch bytes
#define CHUNK  48

// smem: 3 A buffers (hi+lo 14336 each -> 28672/buf), then B region:
//   mode-a: 3 buffers of (hi 7168 + lo 7168) = 14336 each
//   mode-b: 2 buffers of (hi 6912(+pad) @0, lo @+7168) within same spacing
#define ABUF_STRIDE 28672
#define A_LO_OFF    14336
#define B_BASE      86016
#define BBUF_STRIDE 14336
#define B_LO_OFF    7168
#define SMEM_DYN    (B_BASE + 3 * BBUF_STRIDE)   // 129024

// ---------------------------------------------------------------------------
__device__ __align__(16) ushortt g_Cb[2][NA * DD];
__device__ __align__(16) ushortt g_Pb[2][3][NA * EE];
__device__ __align__(16) ushortt g_Qb[2][2][NA * EE];
__device__ __align__(16) float   g_Qv[NA * EE];
__device__ __align__(16) float   g_S[NH * NA * NA];
__device__ unsigned g_mask[NA * 8];
__device__ __align__(16) float   g_Wfin[EE * 6];
__device__ float    g_bfin[6];

// ---------------------------------------------------------------------------
__device__ __forceinline__ unsigned su32(const void* p) {
    unsigned a;
    asm("{ .reg .u64 t; cvta.to.shared.u64 t, %1; cvt.u32.u64 %0, t; }"
        : "=r"(a) : "l"(p));
    return a;
}
__device__ __forceinline__ void cpa16(unsigned s, const void* g) {
    asm volatile("cp.async.cg.shared.global [%0], [%1], 16;" :: "r"(s), "l"(g));
}
#define CPA_COMMIT() asm volatile("cp.async.commit_group;" ::: "memory")
__device__ __forceinline__ void cpwait_n(int w) {
    if (w >= 2)      asm volatile("cp.async.wait_group 2;" ::: "memory");
    else if (w == 1) asm volatile("cp.async.wait_group 1;" ::: "memory");
    else             asm volatile("cp.async.wait_group 0;" ::: "memory");
}

__device__ __forceinline__ void mma16816(float c[4],
    unsigned a0, unsigned a1, unsigned a2, unsigned a3,
    unsigned b0, unsigned b1)
{
    asm volatile(
        "mma.sync.aligned.m16n8k16.row.col.f32.bf16.bf16.f32 "
        "{%0,%1,%2,%3}, {%4,%5,%6,%7}, {%8,%9}, {%0,%1,%2,%3};"
        : "+f"(c[0]), "+f"(c[1]), "+f"(c[2]), "+f"(c[3])
        : "r"(a0), "r"(a1), "r"(a2), "r"(a3), "r"(b0), "r"(b1));
}
__device__ __forceinline__ void ldmx4t(unsigned& r0, unsigned& r1,
                                       unsigned& r2, unsigned& r3, unsigned a)
{
    asm volatile("ldmatrix.sync.aligned.m8n8.x4.trans.shared.b16 {%0,%1,%2,%3}, [%4];"
                 : "=r"(r0), "=r"(r1), "=r"(r2), "=r"(r3) : "r"(a));
}

__device__ __forceinline__ void split1(float v, ushortt& h, ushortt& l) {
    __nv_bfloat16 hb = __float2bfloat16(v);
    float r = v - __bfloat162float(hb);
    __nv_bfloat16 lb = __float2bfloat16(r);
    h = __bfloat16_as_ushort(hb);
    l = __bfloat16_as_ushort(lb);
}
__device__ __forceinline__ void split2(float v0, float v1, unsigned& h, unsigned& l) {
    ushortt h0, l0, h1, l1;
    split1(v0, h0, l0); split1(v1, h1, l1);
    h = ((unsigned)h1 << 16) | h0;
    l = ((unsigned)l1 << 16) | l0;
}

// ---------------------------------------------------------------------------
__device__ __forceinline__ void stageA_cp(const ushortt* __restrict__ AH,
                                          const ushortt* __restrict__ AL,
                                          int lda, int k0, unsigned abuf, int tid)
{
    for (int idx = tid; idx < 768; idx += NTH) {
        const int r = idx / 6, cc = idx % 6;
        const unsigned d = abuf + r * 112 + cc * 16;
        const int go = r * lda + k0 + cc * 8;
        cpa16(d,            AH + go);
        cpa16(d + A_LO_OFF, AL + go);
    }
}
__device__ __forceinline__ void stageB_cp(const ushortt* __restrict__ BH,
                                          const ushortt* __restrict__ BL,
                                          int ldb, int k0, unsigned bbuf, int tid)
{
    for (int idx = tid; idx < 384; idx += NTH) {
        const int r = idx / 6, cc = idx % 6;
        const unsigned d = bbuf + r * 112 + cc * 16;
        const int go = r * ldb + k0 + cc * 8;
        cpa16(d,            BH + go);
        cpa16(d + B_LO_OFF, BL + go);
    }
}
__device__ __forceinline__ void ldgB_w(const float* __restrict__ W, int ldw,
                                       int n0, int k0, float4 br[2], int tid)
{
#pragma unroll
    for (int t = 0; t < 2; ++t) {
        const int idx = tid + t * NTH;
        if (idx < 768) {
            const int r = idx >> 4, c4 = (idx & 15) * 4;
            br[t] = *(const float4*)&W[(size_t)(k0 + r) * ldw + n0 + c4];
        }
    }
}
__device__ __forceinline__ void stsB_w(const float4 br[2], char* bbuf, int tid)
{
#pragma unroll
    for (int t = 0; t < 2; ++t) {
        const int idx = tid + t * NTH;
        if (idx < 768) {
            const int r = idx >> 4, c4 = (idx & 15) * 4;
            unsigned h0, l0, h1, l1;
            split2(br[t].x, br[t].y, h0, l0);
            split2(br[t].z, br[t].w, h1, l1);
            char* p = bbuf + r * BPITCH + c4 * 2;
            *(uint2*)p = make_uint2(h0, h1);
            *(uint2*)(p + B_LO_OFF) = make_uint2(l0, l1);
        }
    }
}

__device__ __forceinline__ void load_afrag(const char* abuf, int wm, int g, int tg,
                                           int kk, unsigned ah[2][4], unsigned al[2][4])
{
    const unsigned* AH = (const unsigned*)abuf;
    const unsigned* AL = (const unsigned*)(abuf + A_LO_OFF);
    const int kc = kk * 8 + tg;
#pragma unroll
    for (int i = 0; i < 2; ++i) {
        const int r0 = (wm * 32 + i * 16 + g) * PITCHU;
        const int r1 = r0 + 8 * PITCHU;
        ah[i][0] = AH[r0 + kc];     ah[i][1] = AH[r1 + kc];
        ah[i][2] = AH[r0 + kc + 4]; ah[i][3] = AH[r1 + kc + 4];
        al[i][0] = AL[r0 + kc];     al[i][1] = AL[r1 + kc];
        al[i][2] = AL[r0 + kc + 4]; al[i][3] = AL[r1 + kc + 4];
    }
}

__device__ __forceinline__ void mma_chunk_a(const char* abuf, const char* bbuf,
                                            int wm, int wn, int g, int tg,
                                            float acc[2][2][4])
{
    const unsigned* BH = (const unsigned*)bbuf;
    const unsigned* BL = (const unsigned*)(bbuf + B_LO_OFF);
#pragma unroll
    for (int kk = 0; kk < 3; ++kk) {
        unsigned ah[2][4], al[2][4];
        load_afrag(abuf, wm, g, tg, kk, ah, al);
        const int kc = kk * 8 + tg;
#pragma unroll
        for (int j = 0; j < 2; ++j) {
            const int nrow = (wn * 16 + j * 8 + g) * PITCHU;
            const unsigned bh0 = BH[nrow + kc], bh1 = BH[nrow + kc + 4];
            const unsigned bl0 = BL[nrow + kc], bl1 = BL[nrow + kc + 4];
#pragma unroll
            for (int i = 0; i < 2; ++i) {
                mma16816(acc[i][j], ah[i][0], ah[i][1], ah[i][2], ah[i][3], bh0, bh1);
                mma16816(acc[i][j], ah[i][0], ah[i][1], ah[i][2], ah[i][3], bl0, bl1);
                mma16816(acc[i][j], al[i][0], al[i][1], al[i][2], al[i][3], bh0, bh1);
            }
        }
    }
}

__device__ __forceinline__ void mma_chunk_w(const char* abuf, unsigned bbuf_u32,
                                            int wm, int g, int tg,
                                            int krow_off, int joff_b,
                                            float acc[2][2][4])
{
#pragma unroll
    for (int kk = 0; kk < 3; ++kk) {
        unsigned ah[2][4], al[2][4];
        load_afrag(abuf, wm, g, tg, kk, ah, al);
        const unsigned ba = bbuf_u32 +
            (unsigned)((kk * 16 + krow_off) * BPITCH) + joff_b;
        unsigned bh0, bh1, bh2, bh3, bl0, bl1, bl2, bl3;
        ldmx4t(bh0, bh1, bh2, bh3, ba);
        ldmx4t(bl0, bl1, bl2, bl3, ba + B_LO_OFF);
#pragma unroll
        for (int i = 0; i < 2; ++i) {
            mma16816(acc[i][0], ah[i][0], ah[i][1], ah[i][2], ah[i][3], bh0, bh1);
            mma16816(acc[i][0], ah[i][0], ah[i][1], ah[i][2], ah[i][3], bl0, bl1);
            mma16816(acc[i][0], al[i][0], al[i][1], al[i][2], al[i][3], bh0, bh1);
            mma16816(acc[i][1], ah[i][0], ah[i][1], ah[i][2], ah[i][3], bh2, bh3);
            mma16816(acc[i][1], ah[i][0], ah[i][1], ah[i][2], ah[i][3], bl2, bl3);
            mma16816(acc[i][1], al[i][0], al[i][1], al[i][2], al[i][3], bh2, bh3);
        }
    }
}

// ---------------------------------------------------------------------------
// 3-stage pipelined tile, activations both sides (B via cp.async).
// ---------------------------------------------------------------------------
template<int NC>
__device__ __forceinline__ void run_tile_a(
    const ushortt* AH, const ushortt* AL, int lda,
    const ushortt* BH, const ushortt* BL, int ldb,
    char* gs, unsigned gs_u32, int tid, float acc[2][2][4])
{
    const int wm = (tid >> 5) & 3, wn = tid >> 7;
    const int g = (tid & 31) >> 2, tg = tid & 3;
#pragma unroll
    for (int p = 0; p < 3 && p < NC; ++p) {
        stageA_cp(AH, AL, lda, p * CHUNK, gs_u32 + p * ABUF_STRIDE, tid);
        stageB_cp(BH, BL, ldb, p * CHUNK, gs_u32 + B_BASE + p * BBUF_STRIDE, tid);
        CPA_COMMIT();
    }
#pragma unroll
    for (int c = 0; c < NC; ++c) {
        const int issued = (c + 3 < NC) ? (c + 3) : NC;
        cpwait_n(issued - c - 1);
        __syncthreads();
        mma_chunk_a(gs + (c % 3) * ABUF_STRIDE,
                    gs + B_BASE + (c % 3) * BBUF_STRIDE, wm, wn, g, tg, acc);
        __syncthreads();
        if (c + 3 < NC) {
            stageA_cp(AH, AL, lda, (c + 3) * CHUNK, gs_u32 + (c % 3) * ABUF_STRIDE, tid);
            stageB_cp(BH, BL, ldb, (c + 3) * CHUNK,
                      gs_u32 + B_BASE + (c % 3) * BBUF_STRIDE, tid);
            CPA_COMMIT();
        }
    }
}

// ---------------------------------------------------------------------------
// 3-stage pipelined tile, B = fp32 weights [k][n] (register prefetch + stsB).
// ---------------------------------------------------------------------------
template<int NC>
__device__ __forceinline__ void run_tile_w(
    const ushortt* AH, const ushortt* AL, int lda,
    const float* W, int ldw, int n0,
    char* gs, unsigned gs_u32, int tid, float acc[2][2][4])
{
    const int lane = tid & 31;
    const int wm = (tid >> 5) & 3, wn = tid >> 7;
    const int g = lane >> 2, tg = lane & 3;
    const int krow_off = ((lane >> 3) & 1) * 8 + (lane & 7);
    const int joff_b = (wn * 16 + ((lane >> 4) & 1) * 8) * 2;

#pragma unroll
    for (int p = 0; p < 3 && p < NC; ++p) {
        stageA_cp(AH, AL, lda, p * CHUNK, gs_u32 + p * ABUF_STRIDE, tid);
        CPA_COMMIT();
    }
    float4 br[2];
    ldgB_w(W, ldw, n0, 0, br, tid);
    stsB_w(br, gs + B_BASE, tid);                 // chunk 0 -> bbuf 0
    if (NC > 1) ldgB_w(W, ldw, n0, CHUNK, br, tid);

#pragma unroll
    for (int c = 0; c < NC; ++c) {
        const int issued = (c + 3 < NC) ? (c + 3) : NC;
        cpwait_n(issued - c - 1);
        __syncthreads();
        mma_chunk_w(gs + (c % 3) * ABUF_STRIDE,
                    gs_u32 + B_BASE + (c % 2) * BBUF_STRIDE,
                    wm, g, tg, krow_off, joff_b, acc);
        __syncthreads();
        if (c + 1 < NC) stsB_w(br, gs + B_BASE + ((c + 1) % 2) * BBUF_STRIDE, tid);
        if (c + 2 < NC) ldgB_w(W, ldw, n0, (c + 2) * CHUNK, br, tid);
        if (c + 3 < NC) {
            stageA_cp(AH, AL, lda, (c + 3) * CHUNK, gs_u32 + (c % 3) * ABUF_STRIDE, tid);
            CPA_COMMIT();
        }
    }
}

// ---------------------------------------------------------------------------
// LAUNCH 1: setup (obs encode, head combine, mask). 18 blocks x 512.
// ---------------------------------------------------------------------------
__global__ __launch_bounds__(NTH)
void k_setup(const float* __restrict__ hid, const float* __restrict__ act,
             const int* __restrict__ state,
             const float* __restrict__ W_enc, const float* __restrict__ b_enc,
             const float* __restrict__ Wo, const float* __restrict__ bo,
             const float* __restrict__ W_O,
             const float* __restrict__ W_val, const float* __restrict__ W_adv)
{
    __shared__ float W2[EE * 6];
    const int tid = threadIdx.x;
    const int bx  = blockIdx.x;

    if (bx < 8) {
        const int base = bx * 32;
        {
            const int ai = base + (tid >> 4);
            const int c  = tid & 15;
            float o = b_enc[c];
            for (int d = 0; d < HID; ++d)
                o += hid[ai * HID + d] * W_enc[d * 16 + c];
            ushortt h, l; split1(o, h, l);
            g_Cb[0][ai * DD + c] = h;
            g_Cb[1][ai * DD + c] = l;
        }
        for (int idx = tid; idx < 32 * 32; idx += NTH) {
            const int ai = base + (idx >> 5), c4 = (idx & 31) * 4;
            float4 v = *(const float4*)&act[ai * HID + c4];
            unsigned h0, l0, h1, l1;
            split2(v.x, v.y, h0, l0);
            split2(v.z, v.w, h1, l1);
            const int o = ai * DD + 16 + c4;
            *(uint2*)&g_Cb[0][o] = make_uint2(h0, h1);
            *(uint2*)&g_Cb[1][o] = make_uint2(l0, l1);
        }
    } else if (bx < 17) {
        const int part = bx - 8;
        for (int r = tid; r < EE; r += NTH) {
            float a[6] = {};
            for (int k4 = 0; k4 < DD; k4 += 4) {
                float4 w4 = *(const float4*)&W_O[r * DD + k4];
                const float wv[4] = {w4.x, w4.y, w4.z, w4.w};
#pragma unroll
                for (int u = 0; u < 4; ++u) {
                    const int k = k4 + u;
                    a[0] += wv[u] * W_val[k];
#pragma unroll
                    for (int j = 0; j < ACT; ++j) a[1 + j] += wv[u] * W_adv[k * ACT + j];
                }
            }
#pragma unroll
            for (int j = 0; j < 6; ++j) W2[r * 6 + j] = a[j];
        }
        __syncthreads();
        {
            const int e  = part * 64 + (tid >> 3);
            const int f0 = (tid & 7) * 72;
            float a[6] = {};
            for (int f = f0; f < f0 + 72; ++f) {
                const float w = Wo[e * EE + f];
#pragma unroll
                for (int j = 0; j < 6; ++j) a[j] += w * W2[f * 6 + j];
            }
#pragma unroll
            for (int j = 0; j < 6; ++j) {
                a[j] += __shfl_xor_sync(0xffffffffu, a[j], 1);
                a[j] += __shfl_xor_sync(0xffffffffu, a[j], 2);
                a[j] += __shfl_xor_sync(0xffffffffu, a[j], 4);
            }
            if ((tid & 7) == 0) {
#pragma unroll
                for (int j = 0; j < 6; ++j) g_Wfin[e * 6 + j] = a[j];
            }
        }
        if (part == 0 && tid < 6) {
            float s = 0.f;
            for (int f = 0; f < EE; ++f) s += bo[f] * W2[f * 6 + tid];
            g_bfin[tid] = s;
        }
    } else {
        int* px = (int*)W2; int* py = px + NA;
        if (tid < NA) { px[tid] = state[2 * tid]; py[tid] = state[2 * tid + 1]; }
        __syncthreads();
        if (tid < NA) {
            unsigned wb[8] = {0, 0, 0, 0, 0, 0, 0, 0};
            const int xi = px[tid], yi = py[tid];
            for (int j = tid + 1; j < NA; ++j) {
                const int dx = abs(xi - px[j]);
                const int dy = abs(yi - py[j]);
                if (dx <= OBS_RX && dy <= OBS_RY) wb[j >> 5] |= (1u << (j & 31));
            }
#pragma unroll
            for (int q = 0; q < 8; ++q) g_mask[tid * 8 + q] = wb[q];
        }
    }
}

// ---------------------------------------------------------------------------
// LAUNCH 2: B1  P(z) = C @ Wz + bz   (54 blocks x 512, K=144 -> NC=3)
// ---------------------------------------------------------------------------
__global__ __launch_bounds__(NTH)
void k_b1(const float* __restrict__ Wq, const float* __restrict__ bq,
          const float* __restrict__ Wk, const float* __restrict__ bk,
          const float* __restrict__ Wv, const float* __restrict__ bv)
{
    extern __shared__ char gs[];
    const int tid = threadIdx.x;
    const int bx  = blockIdx.x;
    const int wid = tid >> 5, lane = tid & 31;
    const int wm = wid & 3, wn = wid >> 2;
    const int g = lane >> 2, tg = lane & 3;
    const unsigned gs_u32 = su32(gs);

    const int z  = bx / 18, r = bx % 18;
    const int m0 = (r / 9) * 128, n0 = (r % 9) * 64;
    const float* Wz = (z == 0) ? Wq : (z == 1) ? Wk : Wv;
    const float* bz = (z == 0) ? bq : (z == 1) ? bk : bv;
    float acc[2][2][4] = {};
    run_tile_w<3>(&g_Cb[0][0] + m0 * DD, &g_Cb[1][0] + m0 * DD, DD,
                  Wz, EE, n0, gs, gs_u32, tid, acc);
#pragma unroll
    for (int i = 0; i < 2; ++i) {
        const int row = m0 + wm * 32 + i * 16 + g;
#pragma unroll
        for (int j = 0; j < 2; ++j) {
            const int col = n0 + wn * 16 + j * 8 + 2 * tg;
            const float b0 = bz[col], b1 = bz[col + 1];
            unsigned h, l;
            split2(acc[i][j][0] + b0, acc[i][j][1] + b1, h, l);
            *(unsigned*)&g_Pb[0][z][row * EE + col] = h;
            *(unsigned*)&g_Pb[1][z][row * EE + col] = l;
            split2(acc[i][j][2] + b0, acc[i][j][3] + b1, h, l);
            *(unsigned*)&g_Pb[0][z][(row + 8) * EE + col] = h;
            *(unsigned*)&g_Pb[1][z][(row + 8) * EE + col] = l;
        }
    }
}

// ---------------------------------------------------------------------------
// LAUNCH 3: B2  qkv(z) = P(z) @ Wiz + biz  (54 blocks x 512, K=576 -> NC=12)
// ---------------------------------------------------------------------------
__global__ __launch_bounds__(NTH)
void k_b2(const float* __restrict__ Wiq, const float* __restrict__ biq,
          const float* __restrict__ Wik, const float* __restrict__ bik,
          const float* __restrict__ Wiv, const float* __restrict__ biv)
{
    extern __shared__ char gs[];
    const int tid = threadIdx.x;
    const int bx  = blockIdx.x;
    const int wid = tid >> 5, lane = tid & 31;
    const int wm = wid & 3, wn = wid >> 2;
    const int g = lane >> 2, tg = lane & 3;
    const unsigned gs_u32 = su32(gs);

    const int z  = bx / 18, r = bx % 18;
    const int m0 = (r / 9) * 128, n0 = (r % 9) * 64;
    const float* Wiz = (z == 0) ? Wiq : (z == 1) ? Wik : Wiv;
    const float* biz = (z == 0) ? biq : (z == 1) ? bik : biv;
    float acc[2][2][4] = {};
    run_tile_w<12>(&g_Pb[0][z][0] + m0 * EE, &g_Pb[1][z][0] + m0 * EE, EE,
                   Wiz, EE, n0, gs, gs_u32, tid, acc);
#pragma unroll
    for (int i = 0; i < 2; ++i) {
        const int row = m0 + wm * 32 + i * 16 + g;
#pragma unroll
        for (int j = 0; j < 2; ++j) {
            const int col = n0 + wn * 16 + j * 8 + 2 * tg;
            const float b0 = biz[col], b1 = biz[col + 1];
            const float v0 = acc[i][j][0] + b0, v1 = acc[i][j][1] + b1;
            const float v2 = acc[i][j][2] + b0, v3 = acc[i][j][3] + b1;
            if (z < 2) {
                unsigned h, l;
                split2(v0, v1, h, l);
                *(unsigned*)&g_Qb[0][z][row * EE + col] = h;
                *(unsigned*)&g_Qb[1][z][row * EE + col] = l;
                split2(v2, v3, h, l);
                *(unsigned*)&g_Qb[0][z][(row + 8) * EE + col] = h;
                *(unsigned*)&g_Qb[1][z][(row + 8) * EE + col] = l;
            } else {
                *(float2*)&g_Qv[row * EE + col]       = make_float2(v0, v1);
                *(float2*)&g_Qv[(row + 8) * EE + col] = make_float2(v2, v3);
            }
        }
    }
}

// ---------------------------------------------------------------------------
// LAUNCH 4: S[h] = (1/12) q2_h @ k2_h^T  (32 blocks x 512, K=144 -> NC=3)
// ---------------------------------------------------------------------------
__global__ __launch_bounds__(NTH)
void k_s()
{
    extern __shared__ char gs[];
    const int tid = threadIdx.x;
    const int bx  = blockIdx.x;
    const int wid = tid >> 5, lane = tid & 31;
    const int wm = wid & 3, wn = wid >> 2;
    const int g = lane >> 2, tg = lane & 3;
    const unsigned gs_u32 = su32(gs);

    const int h  = bx / 8, r = bx % 8;
    const int m0 = (r / 4) * 128, n0 = (r % 4) * 64;
    float acc[2][2][4] = {};
    run_tile_a<3>(&g_Qb[0][0][0] + m0 * EE + h * HDH, &g_Qb[1][0][0] + m0 * EE + h * HDH, EE,
                  &g_Qb[0][1][0] + n0 * EE + h * HDH, &g_Qb[1][1][0] + n0 * EE + h * HDH, EE,
                  gs, gs_u32, tid, acc);
    float* Cd = g_S + h * NA * NA;
#pragma unroll
    for (int i = 0; i < 2; ++i) {
        const int row = m0 + wm * 32 + i * 16 + g;
#pragma unroll
        for (int j = 0; j < 2; ++j) {
            const int col = n0 + wn * 16 + j * 8 + 2 * tg;
            *(float2*)&Cd[row * NA + col] =
                make_float2(acc[i][j][0] * (1.f / 12.f), acc[i][j][1] * (1.f / 12.f));
            *(float2*)&Cd[(row + 8) * NA + col] =
                make_float2(acc[i][j][2] * (1.f / 12.f), acc[i][j][3] * (1.f / 12.f));
        }
    }
}

// ---------------------------------------------------------------------------
// LAUNCH 5: per-agent masked softmax-sum + context + final head.
// ---------------------------------------------------------------------------
#define DTH 256
__global__ __launch_bounds__(DTH)
void k_de(const float* __restrict__ b_val, const float* __restrict__ b_adv,
          float* __restrict__ out)
{
    __shared__ float w[NH * NA];
    __shared__ int   Jl[NA];
    __shared__ float red[6];
    __shared__ int   s_sn;

    const int tid  = threadIdx.x;
    const int lane = tid & 31;
    const int i    = blockIdx.x;

    for (int q = tid; q < NH * NA; q += DTH) w[q] = 0.f;
    if (tid < 6) red[tid] = 0.f;
    if (tid == 0) {
        int n = 0;
        for (int q = 0; q < 8; ++q) {
            unsigned bits = g_mask[i * 8 + q];
            while (bits) {
                const int b = __ffs(bits) - 1;
                Jl[n++] = q * 32 + b;
                bits &= bits - 1;
            }
        }
        s_sn = n;
    }
    __syncthreads();
    const int n = s_sn;
    float a6[6] = {};
    if (n > 0) {
        for (int p = tid; p < NH * n; p += DTH) {
            const int h  = p & 3;
            const int jj = Jl[p >> 2];
            const float* row = g_S + h * NA * NA + jj * NA;
            float m = -1e30f;
            for (int q = 0; q < n; ++q) m = fmaxf(m, row[Jl[q]]);
            float sum = 0.f;
            for (int q = 0; q < n; ++q) sum += expf(row[Jl[q]] - m);
            const float inv = 1.f / sum;
            for (int q = 0; q < n; ++q)
                atomicAdd(&w[h * NA + q], expf(row[Jl[q]] - m) * inv);
        }
        __syncthreads();
        for (int e = tid; e < EE; e += DTH) {
            const int h = e / HDH;
            float G = 0.f;
            for (int q = 0; q < n; ++q)
                G += w[h * NA + q] * g_Qv[Jl[q] * EE + e];
            const float* Wr = g_Wfin + e * 6;
#pragma unroll
            for (int j = 0; j < 6; ++j) a6[j] += G * Wr[j];
        }
    }
#pragma unroll
    for (int j = 0; j < 6; ++j)
#pragma unroll
        for (int o = 16; o > 0; o >>= 1)
            a6[j] += __shfl_xor_sync(0xffffffffu, a6[j], o);
    if (lane == 0) {
#pragma unroll
        for (int j = 0; j < 6; ++j) atomicAdd(&red[j], a6[j]);
    }
    __syncthreads();
    if (tid == 0) {
        const float c = (float)n;
        const float V = red[0] + c * g_bfin[0] + b_val[0];
        float A[ACT], mean = 0.f;
#pragma unroll
        for (int j = 0; j < ACT; ++j) {
            A[j] = red[1 + j] + c * g_bfin[1 + j] + b_adv[j];
            mean += A[j];
        }
        mean *= (1.f / ACT);
#pragma unroll
        for (int j = 0; j < ACT; ++j) out[i * ACT + j] = V + A[j] - mean;
    }
}

// ---------------------------------------------------------------------------
extern "C" void kernel_launch(void* const* d_in, const int* in_sizes, int n_in,
                              void* d_out, int out_size)
{
    const float *hid, *act, *W_enc, *b_enc, *Wq, *bq, *Wk, *bk, *Wv, *bv;
    const float *Wiq, *biq, *Wik, *bik, *Wiv, *biv, *Wo, *bo, *W_O;
    const float *W_val, *b_val, *W_adv, *b_adv;
    const int* state;

    if (n_in >= 3 && in_sizes[2] == 512) {
        hid   = (const float*)d_in[0];  act  = (const float*)d_in[1];
        state = (const int*)  d_in[2];
        W_enc = (const float*)d_in[3];  b_enc = (const float*)d_in[4];
        Wq  = (const float*)d_in[5];    bq  = (const float*)d_in[6];
        Wk  = (const float*)d_in[7];    bk  = (const float*)d_in[8];
        Wv  = (const float*)d_in[9];    bv  = (const float*)d_in[10];
        Wiq = (const float*)d_in[11];   biq = (const float*)d_in[12];
        Wik = (const float*)d_in[13];   bik = (const float*)d_in[14];
        Wiv = (const float*)d_in[15];   biv = (const float*)d_in[16];
        Wo  = (const float*)d_in[17];   bo  = (const float*)d_in[18];
        W_O = (const float*)d_in[19];
        W_val = (const float*)d_in[20]; b_val = (const float*)d_in[21];
        W_adv = (const float*)d_in[22]; b_adv = (const float*)d_in[23];
    } else {
        hid   = (const float*)d_in[0];  act  = (const float*)d_in[1];
        W_enc = (const float*)d_in[2];  b_enc = (const float*)d_in[3];
        Wq  = (const float*)d_in[4];    bq  = (const float*)d_in[5];
        Wk  = (const float*)d_in[6];    bk  = (const float*)d_in[7];
        Wv  = (const float*)d_in[8];    bv  = (const float*)d_in[9];
        Wiq = (const float*)d_in[10];   biq = (const float*)d_in[11];
        Wik = (const float*)d_in[12];   bik = (const float*)d_in[13];
        Wiv = (const float*)d_in[14];   biv = (const float*)d_in[15];
        Wo  = (const float*)d_in[16];   bo  = (const float*)d_in[17];
        W_O = (const float*)d_in[18];
        W_val = (const float*)d_in[19]; b_val = (const float*)d_in[20];
        W_adv = (const float*)d_in[21]; b_adv = (const float*)d_in[22];
        state = (const int*)  d_in[23];
    }

    static bool attr_set = false;
    if (!attr_set) {
        cudaFuncSetAttribute(k_b1, cudaFuncAttributeMaxDynamicSharedMemorySize, SMEM_DYN);
        cudaFuncSetAttribute(k_b2, cudaFuncAttributeMaxDynamicSharedMemorySize, SMEM_DYN);
        cudaFuncSetAttribute(k_s,  cudaFuncAttributeMaxDynamicSharedMemorySize, SMEM_DYN);
        attr_set = true;
    }

    k_setup<<<18, NTH>>>(hid, act, state, W_enc, b_enc, Wo, bo, W_O, W_val, W_adv);
    k_b1<<<54, NTH, SMEM_DYN>>>(Wq, bq, Wk, bk, Wv, bv);
    k_b2<<<54, NTH, SMEM_DYN>>>(Wiq, biq, Wik, bik, Wiv, biv);
    k_s<<<32, NTH, SMEM_DYN>>>();
    k_de<<<NA, DTH>>>(b_val, b_adv, (float*)d_out);
}